// round 12
// baseline (speedup 1.0000x reference)
#include <cuda_runtime.h>
#include <cuda_bf16.h>
#include <cuda_fp16.h>
#include <math.h>
#include <cstdint>

#define EPSV 1e-5f

// ---------------- scratch (device globals; allocation-free) ----------------
__device__ __nv_bfloat16 g_qb[16 * 4096 * 64];   // q: [bh][n][c], pre-scaled 0.125*log2e
__device__ uint4 g_kf4[16 * 512 * 2 * 32];       // K frags (bf16): [bh][kt][sp][lane]
__device__ uint4 g_vf4[16 * 32 * 8 * 4 * 32];    // V frags (fp16): [bh][chunk][ct][sp][lane]
__device__ __nv_bfloat16 g_ao[4 * 256 * 4096];   // attention out [b][c][n] bf16
__device__ float g_part[32 * 16 * 2];
__device__ float g_mean[32];
__device__ float g_rstd[32];

// ======================= helpers =======================
__device__ __forceinline__ uint32_t pbf2(float lo, float hi) {
    __nv_bfloat162 t = __floats2bfloat162_rn(lo, hi);
    return *(uint32_t*)&t;
}
__device__ __forceinline__ uint32_t ph2(float lo, float hi) {
    __half2 t = __floats2half2_rn(lo, hi);
    return *(uint32_t*)&t;
}
__device__ __forceinline__ uint32_t ex2h2(uint32_t h2) {
    uint32_t r;
    asm("ex2.approx.f16x2 %0, %1;" : "=r"(r) : "r"(h2));
    return r;
}
__device__ __forceinline__ void mma_bf16(float d[4], const uint32_t a0, const uint32_t a1,
                                         const uint32_t a2, const uint32_t a3,
                                         const uint32_t b0, const uint32_t b1) {
    asm volatile("mma.sync.aligned.m16n8k16.row.col.f32.bf16.bf16.f32 "
                 "{%0,%1,%2,%3}, {%4,%5,%6,%7}, {%8,%9}, {%0,%1,%2,%3};"
                 : "+f"(d[0]), "+f"(d[1]), "+f"(d[2]), "+f"(d[3])
                 : "r"(a0), "r"(a1), "r"(a2), "r"(a3), "r"(b0), "r"(b1));
}
__device__ __forceinline__ void mma_f16(float d[4], const uint32_t a0, const uint32_t a1,
                                        const uint32_t a2, const uint32_t a3,
                                        const uint32_t b0, const uint32_t b1) {
    asm volatile("mma.sync.aligned.m16n8k16.row.col.f32.f16.f16.f32 "
                 "{%0,%1,%2,%3}, {%4,%5,%6,%7}, {%8,%9}, {%0,%1,%2,%3};"
                 : "+f"(d[0]), "+f"(d[1]), "+f"(d[2]), "+f"(d[3])
                 : "r"(a0), "r"(a1), "r"(a2), "r"(a3), "r"(b0), "r"(b1));
}
__device__ __forceinline__ void cp16(uint32_t saddr, const void* gaddr) {
    asm volatile("cp.async.cg.shared.global [%0], [%1], 16;" :: "r"(saddr), "l"(gaddr));
}
#define CP_COMMIT() asm volatile("cp.async.commit_group;" ::: "memory")
#define CP_WAIT1()  asm volatile("cp.async.wait_group 1;" ::: "memory")

// ---------------- GroupNorm stats ----------------
__global__ void gn_partial(const float* __restrict__ x) {
    int bg = blockIdx.x;
    int chunk = blockIdx.y;
    const float4* p = (const float4*)(x + (size_t)bg * 32 * 4096 + (size_t)chunk * 8192);
    float s = 0.f, q = 0.f;
#pragma unroll
    for (int i = 0; i < 8; i++) {
        float4 v = p[threadIdx.x + i * 256];
        s += v.x + v.y + v.z + v.w;
        q += v.x * v.x + v.y * v.y + v.z * v.z + v.w * v.w;
    }
    __shared__ float ss[256], sq[256];
    ss[threadIdx.x] = s; sq[threadIdx.x] = q;
    __syncthreads();
    for (int o = 128; o > 0; o >>= 1) {
        if (threadIdx.x < o) {
            ss[threadIdx.x] += ss[threadIdx.x + o];
            sq[threadIdx.x] += sq[threadIdx.x + o];
        }
        __syncthreads();
    }
    if (threadIdx.x == 0) {
        g_part[(bg * 16 + chunk) * 2 + 0] = ss[0];
        g_part[(bg * 16 + chunk) * 2 + 1] = sq[0];
    }
}

__global__ void gn_finalize() {
    int t = threadIdx.x;
    float s = 0.f, q = 0.f;
#pragma unroll
    for (int i = 0; i < 16; i++) {
        s += g_part[(t * 16 + i) * 2 + 0];
        q += g_part[(t * 16 + i) * 2 + 1];
    }
    const float inv = 1.0f / 131072.0f;
    float mean = s * inv;
    float var = q * inv - mean * mean;
    g_mean[t] = mean;
    g_rstd[t] = rsqrtf(var + EPSV);
}

// ---------------- QKV GEMM (bf16 m16n8k16 mma, GN fused into B staging) -----------
#define QKV_SMEM 35328

__global__ void __launch_bounds__(256) gemm_qkv(const float* __restrict__ W,
                                                const float* __restrict__ x,
                                                const float* __restrict__ bias,
                                                const float* __restrict__ nw,
                                                const float* __restrict__ nbv) {
    extern __shared__ char sm[];
    uint4* Af = (uint4*)sm;
    uint2* Bf = (uint2*)(sm + 4096);
    unsigned short* Ost = (unsigned short*)sm;      // [128][130] 16-bit overlay
    float* sc = (float*)(sm + 33280);
    float* sh = (float*)(sm + 34304);

    const int tid = threadIdx.x, wid = tid >> 5, lane = tid & 31;
    const int gr = lane >> 2, tg = lane & 3;
    const int n0 = blockIdx.x * 128, mb = blockIdx.y, b = blockIdx.z;
    const int wm = wid & 3, wn = wid >> 2;

    {
        int c = tid;
        int bg = b * 8 + (c >> 5);
        float s = g_rstd[bg] * nw[c];
        sc[c] = s;
        sh[c] = nbv[c] - g_mean[bg] * s;
    }
    __syncthreads();

    float acc[2][8][4] = {};
    const float* Abase = W + (size_t)(mb * 128) * 256;

    for (int k0 = 0; k0 < 256; k0 += 16) {
        {
            const float* ap = Abase + (size_t)(wid * 16 + gr) * 256 + k0 + 2 * tg;
            float2 w00 = *(const float2*)ap;
            float2 w10 = *(const float2*)(ap + 8 * 256);
            float2 w01 = *(const float2*)(ap + 8);
            float2 w11 = *(const float2*)(ap + 8 * 256 + 8);
            uint4 u;
            u.x = pbf2(w00.x, w00.y);
            u.y = pbf2(w10.x, w10.y);
            u.z = pbf2(w01.x, w01.y);
            u.w = pbf2(w11.x, w11.y);
            Af[wid * 32 + lane] = u;
        }
#pragma unroll
        for (int i = 0; i < 2; i++) {
            int u_ = wid * 2 + i;
            int n = n0 + u_ * 8 + gr;
            int c0 = k0 + 2 * tg;
            const float* xp = x + ((size_t)(b * 256 + c0)) * 4096 + n;
            float h00 = xp[0] * sc[c0] + sh[c0];
            float h01 = xp[4096] * sc[c0 + 1] + sh[c0 + 1];
            float h10 = xp[8 * 4096] * sc[c0 + 8] + sh[c0 + 8];
            float h11 = xp[9 * 4096] * sc[c0 + 9] + sh[c0 + 9];
            uint2 v;
            v.x = pbf2(h00, h01);
            v.y = pbf2(h10, h11);
            Bf[u_ * 32 + lane] = v;
        }
        __syncthreads();
        uint4 a0 = Af[(wm * 2 + 0) * 32 + lane];
        uint4 a1 = Af[(wm * 2 + 1) * 32 + lane];
#pragma unroll
        for (int u_ = 0; u_ < 8; u_++) {
            uint2 bb = Bf[(wn * 8 + u_) * 32 + lane];
            mma_bf16(acc[0][u_], a0.x, a0.y, a0.z, a0.w, bb.x, bb.y);
            mma_bf16(acc[1][u_], a1.x, a1.y, a1.z, a1.w, bb.x, bb.y);
        }
        __syncthreads();
    }

    const float scale = (mb < 2) ? 0.125f * 1.4426950408889634f : 1.0f;
    const bool v_half = (mb >= 4);
#pragma unroll
    for (int t = 0; t < 2; t++) {
        int o_l = wm * 32 + t * 16 + gr;
        float bi0 = bias[mb * 128 + o_l];
        float bi1 = bias[mb * 128 + o_l + 8];
#pragma unroll
        for (int u_ = 0; u_ < 8; u_++) {
            int n_l = wn * 64 + u_ * 8 + 2 * tg;
            float v00 = (acc[t][u_][0] + bi0) * scale, v01 = (acc[t][u_][1] + bi0) * scale;
            float v10 = (acc[t][u_][2] + bi1) * scale, v11 = (acc[t][u_][3] + bi1) * scale;
            uint32_t w0 = v_half ? ph2(v00, v01) : pbf2(v00, v01);
            uint32_t w1 = v_half ? ph2(v10, v11) : pbf2(v10, v11);
            *(uint32_t*)&Ost[o_l * 130 + n_l] = w0;
            *(uint32_t*)&Ost[(o_l + 8) * 130 + n_l] = w1;
        }
    }
    __syncthreads();

    if (mb < 2) {
#pragma unroll
        for (int p = 0; p < 32; p++) {
            int idx = tid + p * 256;
            int n = idx >> 6;
            int ho = (idx >> 5) & 1;
            int cw = idx & 31;
            unsigned short lo = Ost[(ho * 64 + 2 * cw) * 130 + n];
            unsigned short hi = Ost[(ho * 64 + 2 * cw + 1) * 130 + n];
            uint32_t val = (uint32_t)lo | ((uint32_t)hi << 16);
            int bh = b * 4 + mb * 2 + ho;
            ((uint32_t*)g_qb)[((size_t)bh * 4096 + n0 + n) * 32 + cw] = val;
        }
    } else if (mb < 4) {
#pragma unroll
        for (int p = 0; p < 8; p++) {
            int e = tid + p * 256;
            int ln = e & 31, sp = (e >> 5) & 1, kt = (e >> 6) & 15, ho = e >> 10;
            int egr = ln >> 2, etg = ln & 3;
            int n = kt * 8 + egr;
            uint4 r;
            {
                int c0 = ho * 64 + (2 * sp) * 16 + 2 * etg;
                r.x = (uint32_t)Ost[c0 * 130 + n] | ((uint32_t)Ost[(c0 + 1) * 130 + n] << 16);
                r.y = (uint32_t)Ost[(c0 + 8) * 130 + n] | ((uint32_t)Ost[(c0 + 9) * 130 + n] << 16);
            }
            {
                int c0 = ho * 64 + (2 * sp + 1) * 16 + 2 * etg;
                r.z = (uint32_t)Ost[c0 * 130 + n] | ((uint32_t)Ost[(c0 + 1) * 130 + n] << 16);
                r.w = (uint32_t)Ost[(c0 + 8) * 130 + n] | ((uint32_t)Ost[(c0 + 9) * 130 + n] << 16);
            }
            int bh = b * 4 + (mb & 1) * 2 + ho;
            g_kf4[(((size_t)bh * 512 + (n0 >> 3) + kt) * 2 + sp) * 32 + ln] = r;
        }
    } else {
        int chv = blockIdx.x;
#pragma unroll
        for (int p = 0; p < 8; p++) {
            int e = tid + p * 256;
            int ln = e & 31, sp = (e >> 5) & 3, ct = (e >> 7) & 7, ho = e >> 10;
            int egr = ln >> 2, etg = ln & 3;
            int c = ho * 64 + ct * 8 + egr;
            uint4 r;
            {
                int nn = (2 * sp) * 16 + 2 * etg;
                r.x = *(uint32_t*)&Ost[c * 130 + nn];
                r.y = *(uint32_t*)&Ost[c * 130 + nn + 8];
            }
            {
                int nn = (2 * sp + 1) * 16 + 2 * etg;
                r.z = *(uint32_t*)&Ost[c * 130 + nn];
                r.w = *(uint32_t*)&Ost[c * 130 + nn + 8];
            }
            int bh = b * 4 + (mb - 4) * 2 + ho;
            g_vf4[((((size_t)bh * 32 + chv) * 8 + ct) * 4 + sp) * 32 + ln] = r;
        }
    }
}

// ---------------- Proj GEMM (bf16 mma, bf16 ao input) + bias + residual ----------
__global__ void __launch_bounds__(256) gemm_proj(const float* __restrict__ W,
                                                 const float* __restrict__ bias,
                                                 const float* __restrict__ resid,
                                                 float* __restrict__ outp) {
    __shared__ uint4 Af[8 * 32];
    __shared__ uint2 Bf[16 * 32];
    const int tid = threadIdx.x, wid = tid >> 5, lane = tid & 31;
    const int gr = lane >> 2, tg = lane & 3;
    const int n0 = blockIdx.x * 128, mb = blockIdx.y, b = blockIdx.z;
    const int wm = wid & 3, wn = wid >> 2;

    float acc[2][8][4] = {};
    const float* Abase = W + (size_t)(mb * 128) * 256;

    for (int k0 = 0; k0 < 256; k0 += 16) {
        {
            const float* ap = Abase + (size_t)(wid * 16 + gr) * 256 + k0 + 2 * tg;
            float2 w00 = *(const float2*)ap;
            float2 w10 = *(const float2*)(ap + 8 * 256);
            float2 w01 = *(const float2*)(ap + 8);
            float2 w11 = *(const float2*)(ap + 8 * 256 + 8);
            uint4 u;
            u.x = pbf2(w00.x, w00.y);
            u.y = pbf2(w10.x, w10.y);
            u.z = pbf2(w01.x, w01.y);
            u.w = pbf2(w11.x, w11.y);
            Af[wid * 32 + lane] = u;
        }
#pragma unroll
        for (int i = 0; i < 2; i++) {
            int u_ = wid * 2 + i;
            int n = n0 + u_ * 8 + gr;
            int c0 = k0 + 2 * tg;
            const unsigned short* xp =
                (const unsigned short*)(g_ao + ((size_t)(b * 256 + c0)) * 4096 + n);
            uint2 v;
            v.x = (uint32_t)xp[0] | ((uint32_t)xp[4096] << 16);
            v.y = (uint32_t)xp[8 * 4096] | ((uint32_t)xp[9 * 4096] << 16);
            Bf[u_ * 32 + lane] = v;
        }
        __syncthreads();
        uint4 a0 = Af[(wm * 2 + 0) * 32 + lane];
        uint4 a1 = Af[(wm * 2 + 1) * 32 + lane];
#pragma unroll
        for (int u_ = 0; u_ < 8; u_++) {
            uint2 bb = Bf[(wn * 8 + u_) * 32 + lane];
            mma_bf16(acc[0][u_], a0.x, a0.y, a0.z, a0.w, bb.x, bb.y);
            mma_bf16(acc[1][u_], a1.x, a1.y, a1.z, a1.w, bb.x, bb.y);
        }
        __syncthreads();
    }

#pragma unroll
    for (int t = 0; t < 2; t++) {
        int o = mb * 128 + wm * 32 + t * 16 + gr;
        float bi0 = bias[o], bi1 = bias[o + 8];
#pragma unroll
        for (int u_ = 0; u_ < 8; u_++) {
            size_t off = ((size_t)(b * 256 + o)) * 4096 + n0 + wn * 64 + u_ * 8 + 2 * tg;
            float2 r0 = *(const float2*)(resid + off);
            float2 o0;
            o0.x = acc[t][u_][0] + bi0 + r0.x;
            o0.y = acc[t][u_][1] + bi0 + r0.y;
            *(float2*)(outp + off) = o0;
            size_t off8 = off + 8 * 4096;
            float2 r1 = *(const float2*)(resid + off8);
            float2 o1;
            o1.x = acc[t][u_][2] + bi1 + r1.x;
            o1.y = acc[t][u_][3] + bi1 + r1.y;
            *(float2*)(outp + off8) = o1;
        }
    }
}

// ---------------- flash attention: bf16 QK, f16x2 ex2, fp16 PV, fp32 rowsum -------
// grid (32 q-tiles, 16 bh), 128 thr = 4 warps x 32 q rows.
// smem: 3 stages x (K 16KB | V 16KB) = 96KB. Rowsum: unpack quantized fp16 P
// to fp32 on the (idle) fma/alu pipes — tensor pipe carries only the real math.
#define ATT_SMEM 98304

__global__ void __launch_bounds__(128, 2) attn_mma() {
    extern __shared__ char smc[];
    uint32_t sbase;
    asm("{ .reg .u64 t; cvta.to.shared.u64 t, %1; cvt.u32.u64 %0, t; }" : "=r"(sbase) : "l"(smc));

    const int tid = threadIdx.x, wid = tid >> 5, lane = tid & 31;
    const int gr = lane >> 2, tg = lane & 3;
    const int qt = blockIdx.x, bh = blockIdx.y;
    const int b = bh >> 2, hh = bh & 3;
    const int w32 = wid * 32;

    const __nv_bfloat16* qg = g_qb + ((size_t)bh * 4096 + qt * 128) * 64;
    const uint4* kfg = g_kf4 + (size_t)bh * 32768;
    const uint4* vfg = g_vf4 + (size_t)bh * 32768;

    uint32_t qa[2][4][4];
#pragma unroll
    for (int at = 0; at < 2; at++) {
#pragma unroll
        for (int s = 0; s < 4; s++) {
            const __nv_bfloat16* base = qg + (size_t)(w32 + at * 16 + gr) * 64 + s * 16 + 2 * tg;
            qa[at][s][0] = *(const uint32_t*)(base);
            qa[at][s][1] = *(const uint32_t*)(base + 8 * 64);
            qa[at][s][2] = *(const uint32_t*)(base + 8);
            qa[at][s][3] = *(const uint32_t*)(base + 8 * 64 + 8);
        }
    }

    float oacc[2][8][4] = {};
    float rs[2][2] = {};

#define PREFETCH(ch) do {                                                     \
        int _c = (ch);                                                       \
        if (_c < 32) {                                                       \
            uint32_t _sk = sbase + (uint32_t)(_c % 3) * 32768;               \
            const uint4* _gk = kfg + (size_t)_c * 1024;                      \
            const uint4* _gv = vfg + (size_t)_c * 1024;                      \
            _Pragma("unroll")                                                \
            for (int _i = 0; _i < 8; _i++)                                   \
                cp16(_sk + (tid + _i * 128) * 16, _gk + tid + _i * 128);     \
            _Pragma("unroll")                                                \
            for (int _i = 0; _i < 8; _i++)                                   \
                cp16(_sk + 16384 + (tid + _i * 128) * 16, _gv + tid + _i * 128); \
        }                                                                    \
        CP_COMMIT();                                                         \
    } while (0)

#define S_CALC(dst, g) do {                                                  \
        _Pragma("unroll")                                                    \
        for (int _u = 0; _u < 4; _u++) {                                     \
            uint4 _k0 = Kf4[(((g) * 4 + _u) * 2 + 0) * 32 + lane];           \
            uint4 _k1 = Kf4[(((g) * 4 + _u) * 2 + 1) * 32 + lane];           \
            _Pragma("unroll")                                                \
            for (int _at = 0; _at < 2; _at++) {                              \
                dst[_at][_u][0] = 0.f; dst[_at][_u][1] = 0.f;                \
                dst[_at][_u][2] = 0.f; dst[_at][_u][3] = 0.f;                \
                mma_bf16(dst[_at][_u], qa[_at][0][0], qa[_at][0][1], qa[_at][0][2], qa[_at][0][3], _k0.x, _k0.y); \
                mma_bf16(dst[_at][_u], qa[_at][1][0], qa[_at][1][1], qa[_at][1][2], qa[_at][1][3], _k0.z, _k0.w); \
                mma_bf16(dst[_at][_u], qa[_at][2][0], qa[_at][2][1], qa[_at][2][2], qa[_at][2][3], _k1.x, _k1.y); \
                mma_bf16(dst[_at][_u], qa[_at][3][0], qa[_at][3][1], qa[_at][3][2], qa[_at][3][3], _k1.z, _k1.w); \
            }                                                                \
        }                                                                    \
    } while (0)

    // P = 2^S (f16x2 ex2); fp32 rowsum from the SAME quantized P (fma/alu pipes)
#define E_CALC(pdst, src) do {                                               \
        _Pragma("unroll")                                                    \
        for (int _at = 0; _at < 2; _at++) {                                  \
            _Pragma("unroll")                                                \
            for (int _u = 0; _u < 4; _u++) {                                 \
                uint32_t _h0 = ex2h2(ph2(src[_at][_u][0], src[_at][_u][1])); \
                uint32_t _h1 = ex2h2(ph2(src[_at][_u][2], src[_at][_u][3])); \
                pdst[_at][_u][0] = _h0;                                      \
                pdst[_at][_u][1] = _h1;                                      \
                float2 _f0 = __half22float2(*(__half2*)&_h0);                \
                float2 _f1 = __half22float2(*(__half2*)&_h1);                \
                rs[_at][0] += _f0.x + _f0.y;                                 \
                rs[_at][1] += _f1.x + _f1.y;                                 \
            }                                                                \
        }                                                                    \
    } while (0)

#define V_CALC(g, psrc) do {                                                 \
        _Pragma("unroll")                                                    \
        for (int _ct = 0; _ct < 8; _ct++) {                                  \
            uint4 _v = Vf4[(_ct * 4 + (g)) * 32 + lane];                     \
            _Pragma("unroll")                                                \
            for (int _at = 0; _at < 2; _at++) {                              \
                mma_f16(oacc[_at][_ct], psrc[_at][0][0], psrc[_at][0][1],    \
                        psrc[_at][1][0], psrc[_at][1][1], _v.x, _v.y);       \
                mma_f16(oacc[_at][_ct], psrc[_at][2][0], psrc[_at][2][1],    \
                        psrc[_at][3][0], psrc[_at][3][1], _v.z, _v.w);       \
            }                                                                \
        }                                                                    \
    } while (0)

    PREFETCH(0);
    PREFETCH(1);

    for (int ch = 0; ch < 32; ch++) {
        CP_WAIT1();
        __syncthreads();
        PREFETCH(ch + 2);

        const uint4* Kf4 = (const uint4*)(smc + (ch % 3) * 32768);
        const uint4* Vf4 = (const uint4*)(smc + (ch % 3) * 32768 + 16384);

        float sA[2][4][4], sB[2][4][4];
        uint32_t pA[2][4][2], pB[2][4][2];

        S_CALC(sA, 0);
        E_CALC(pA, sA);
        S_CALC(sB, 1);
        V_CALC(0, pA);
        E_CALC(pB, sB);
        S_CALC(sA, 2);
        V_CALC(1, pB);
        E_CALC(pA, sA);
        S_CALC(sB, 3);
        V_CALC(2, pA);
        E_CALC(pB, sB);
        V_CALC(3, pB);
    }
#undef PREFETCH
#undef S_CALC
#undef E_CALC
#undef V_CALC

    // full row sums (quad lanes share rows)
    float ri[2][2];
#pragma unroll
    for (int at = 0; at < 2; at++) {
#pragma unroll
        for (int r = 0; r < 2; r++) {
            float v = rs[at][r];
            v += __shfl_xor_sync(0xffffffffu, v, 1);
            v += __shfl_xor_sync(0xffffffffu, v, 2);
            ri[at][r] = 1.0f / v;
        }
    }

    // stage O as bf16 [64 c][136 pitch], then coalesced uint4 writes
    unsigned short* Os = (unsigned short*)smc;
    __syncthreads();
#pragma unroll
    for (int at = 0; at < 2; at++) {
#pragma unroll
        for (int ct = 0; ct < 8; ct++) {
            int c = ct * 8 + 2 * tg;
            int q0 = w32 + at * 16 + gr;
            Os[c * 136 + q0] = (unsigned short)(pbf2(oacc[at][ct][0] * ri[at][0], 0.f) & 0xFFFF);
            Os[(c + 1) * 136 + q0] = (unsigned short)(pbf2(oacc[at][ct][1] * ri[at][0], 0.f) & 0xFFFF);
            Os[c * 136 + q0 + 8] = (unsigned short)(pbf2(oacc[at][ct][2] * ri[at][1], 0.f) & 0xFFFF);
            Os[(c + 1) * 136 + q0 + 8] = (unsigned short)(pbf2(oacc[at][ct][3] * ri[at][1], 0.f) & 0xFFFF);
        }
    }
    __syncthreads();

    unsigned short* dst = (unsigned short*)(g_ao + ((size_t)(b * 256 + hh * 64)) * 4096 + qt * 128);
#pragma unroll
    for (int p = 0; p < 8; p++) {
        int idx = tid + p * 128;         // 1024 uint4 = 64 rows x 16
        int c = idx >> 4, q8 = idx & 15;
        uint4 v = *(const uint4*)&Os[c * 136 + q8 * 8];
        *(uint4*)&dst[(size_t)c * 4096 + q8 * 8] = v;
    }
}

// ---------------- launch ----------------
extern "C" void kernel_launch(void* const* d_in, const int* in_sizes, int n_in,
                              void* d_out, int out_size) {
    (void)in_sizes; (void)n_in; (void)out_size;
    const float* x      = (const float*)d_in[0];
    const float* norm_w = (const float*)d_in[1];
    const float* norm_b = (const float*)d_in[2];
    const float* qkv_w  = (const float*)d_in[3];
    const float* qkv_b  = (const float*)d_in[4];
    const float* proj_w = (const float*)d_in[5];
    const float* proj_b = (const float*)d_in[6];
    float* out = (float*)d_out;

    cudaFuncSetAttribute(attn_mma, cudaFuncAttributeMaxDynamicSharedMemorySize, ATT_SMEM);

    gn_partial<<<dim3(32, 16), 256>>>(x);
    gn_finalize<<<1, 32>>>();

    gemm_qkv<<<dim3(32, 6, 4), 256, QKV_SMEM>>>(qkv_w, x, qkv_b, norm_w, norm_b);

    attn_mma<<<dim3(32, 16), 128, ATT_SMEM>>>();

    gemm_proj<<<dim3(32, 2, 4), 256>>>(proj_w, proj_b, x, out);
}

// round 13
// speedup vs baseline: 1.0692x; 1.0692x over previous
#include <cuda_runtime.h>
#include <cuda_bf16.h>
#include <cuda_fp16.h>
#include <math.h>
#include <cstdint>

#define EPSV 1e-5f

// ---------------- scratch (device globals; allocation-free) ----------------
__device__ __nv_bfloat16 g_qb[16 * 4096 * 64];   // q: [bh][n][c], pre-scaled 0.125*log2e
__device__ uint4 g_kf4[16 * 512 * 2 * 32];       // K frags (bf16): [bh][kt][sp][lane]
__device__ uint4 g_vf4[16 * 32 * 8 * 4 * 32];    // V frags (fp16): [bh][chunk][ct][sp][lane]
__device__ __nv_bfloat16 g_ao[4 * 256 * 4096];   // attention out [b][c][n] bf16
__device__ float g_part[32 * 16 * 2];

// ======================= helpers =======================
__device__ __forceinline__ uint32_t pbf2(float lo, float hi) {
    __nv_bfloat162 t = __floats2bfloat162_rn(lo, hi);
    return *(uint32_t*)&t;
}
__device__ __forceinline__ uint32_t ph2(float lo, float hi) {
    __half2 t = __floats2half2_rn(lo, hi);
    return *(uint32_t*)&t;
}
__device__ __forceinline__ uint32_t ex2h2(uint32_t h2) {
    uint32_t r;
    asm("ex2.approx.f16x2 %0, %1;" : "=r"(r) : "r"(h2));
    return r;
}
__device__ __forceinline__ void mma_bf16(float d[4], const uint32_t a0, const uint32_t a1,
                                         const uint32_t a2, const uint32_t a3,
                                         const uint32_t b0, const uint32_t b1) {
    asm volatile("mma.sync.aligned.m16n8k16.row.col.f32.bf16.bf16.f32 "
                 "{%0,%1,%2,%3}, {%4,%5,%6,%7}, {%8,%9}, {%0,%1,%2,%3};"
                 : "+f"(d[0]), "+f"(d[1]), "+f"(d[2]), "+f"(d[3])
                 : "r"(a0), "r"(a1), "r"(a2), "r"(a3), "r"(b0), "r"(b1));
}
__device__ __forceinline__ void mma_f16(float d[4], const uint32_t a0, const uint32_t a1,
                                        const uint32_t a2, const uint32_t a3,
                                        const uint32_t b0, const uint32_t b1) {
    asm volatile("mma.sync.aligned.m16n8k16.row.col.f32.f16.f16.f32 "
                 "{%0,%1,%2,%3}, {%4,%5,%6,%7}, {%8,%9}, {%0,%1,%2,%3};"
                 : "+f"(d[0]), "+f"(d[1]), "+f"(d[2]), "+f"(d[3])
                 : "r"(a0), "r"(a1), "r"(a2), "r"(a3), "r"(b0), "r"(b1));
}
__device__ __forceinline__ void cp16(uint32_t saddr, const void* gaddr) {
    asm volatile("cp.async.cg.shared.global [%0], [%1], 16;" :: "r"(saddr), "l"(gaddr));
}
#define CP_COMMIT() asm volatile("cp.async.commit_group;" ::: "memory")
#define CP_WAIT1()  asm volatile("cp.async.wait_group 1;" ::: "memory")

// ---------------- GroupNorm partial stats ----------------
__global__ void gn_partial(const float* __restrict__ x) {
    int bg = blockIdx.x;
    int chunk = blockIdx.y;
    const float4* p = (const float4*)(x + (size_t)bg * 32 * 4096 + (size_t)chunk * 8192);
    float s = 0.f, q = 0.f;
#pragma unroll
    for (int i = 0; i < 8; i++) {
        float4 v = p[threadIdx.x + i * 256];
        s += v.x + v.y + v.z + v.w;
        q += v.x * v.x + v.y * v.y + v.z * v.z + v.w * v.w;
    }
    __shared__ float ss[256], sq[256];
    ss[threadIdx.x] = s; sq[threadIdx.x] = q;
    __syncthreads();
    for (int o = 128; o > 0; o >>= 1) {
        if (threadIdx.x < o) {
            ss[threadIdx.x] += ss[threadIdx.x + o];
            sq[threadIdx.x] += sq[threadIdx.x + o];
        }
        __syncthreads();
    }
    if (threadIdx.x == 0) {
        g_part[(bg * 16 + chunk) * 2 + 0] = ss[0];
        g_part[(bg * 16 + chunk) * 2 + 1] = sq[0];
    }
}

// ---------------- QKV GEMM (bf16 m16n8k16 mma, GN finalize+apply fused) -----------
#define QKV_SMEM 35328

__global__ void __launch_bounds__(256) gemm_qkv(const float* __restrict__ W,
                                                const float* __restrict__ x,
                                                const float* __restrict__ bias,
                                                const float* __restrict__ nw,
                                                const float* __restrict__ nbv) {
    extern __shared__ char sm[];
    uint4* Af = (uint4*)sm;
    uint2* Bf = (uint2*)(sm + 4096);
    unsigned short* Ost = (unsigned short*)sm;      // [128][130] 16-bit overlay
    float* sc = (float*)(sm + 33280);
    float* sh = (float*)(sm + 34304);

    const int tid = threadIdx.x, wid = tid >> 5, lane = tid & 31;
    const int gr = lane >> 2, tg = lane & 3;
    const int n0 = blockIdx.x * 128, mb = blockIdx.y, b = blockIdx.z;
    const int wm = wid & 3, wn = wid >> 2;

    {
        int c = tid;
        int bg = b * 8 + (c >> 5);
        float s_ = 0.f, q_ = 0.f;
#pragma unroll
        for (int i = 0; i < 16; i++) {
            s_ += g_part[(bg * 16 + i) * 2 + 0];
            q_ += g_part[(bg * 16 + i) * 2 + 1];
        }
        const float inv = 1.0f / 131072.0f;
        float mean = s_ * inv;
        float var = q_ * inv - mean * mean;
        float rstd = rsqrtf(var + EPSV);
        float s = rstd * nw[c];
        sc[c] = s;
        sh[c] = nbv[c] - mean * s;
    }
    __syncthreads();

    float acc[2][8][4] = {};
    const float* Abase = W + (size_t)(mb * 128) * 256;

    for (int k0 = 0; k0 < 256; k0 += 16) {
        {
            const float* ap = Abase + (size_t)(wid * 16 + gr) * 256 + k0 + 2 * tg;
            float2 w00 = *(const float2*)ap;
            float2 w10 = *(const float2*)(ap + 8 * 256);
            float2 w01 = *(const float2*)(ap + 8);
            float2 w11 = *(const float2*)(ap + 8 * 256 + 8);
            uint4 u;
            u.x = pbf2(w00.x, w00.y);
            u.y = pbf2(w10.x, w10.y);
            u.z = pbf2(w01.x, w01.y);
            u.w = pbf2(w11.x, w11.y);
            Af[wid * 32 + lane] = u;
        }
#pragma unroll
        for (int i = 0; i < 2; i++) {
            int u_ = wid * 2 + i;
            int n = n0 + u_ * 8 + gr;
            int c0 = k0 + 2 * tg;
            const float* xp = x + ((size_t)(b * 256 + c0)) * 4096 + n;
            float h00 = xp[0] * sc[c0] + sh[c0];
            float h01 = xp[4096] * sc[c0 + 1] + sh[c0 + 1];
            float h10 = xp[8 * 4096] * sc[c0 + 8] + sh[c0 + 8];
            float h11 = xp[9 * 4096] * sc[c0 + 9] + sh[c0 + 9];
            uint2 v;
            v.x = pbf2(h00, h01);
            v.y = pbf2(h10, h11);
            Bf[u_ * 32 + lane] = v;
        }
        __syncthreads();
        uint4 a0 = Af[(wm * 2 + 0) * 32 + lane];
        uint4 a1 = Af[(wm * 2 + 1) * 32 + lane];
#pragma unroll
        for (int u_ = 0; u_ < 8; u_++) {
            uint2 bb = Bf[(wn * 8 + u_) * 32 + lane];
            mma_bf16(acc[0][u_], a0.x, a0.y, a0.z, a0.w, bb.x, bb.y);
            mma_bf16(acc[1][u_], a1.x, a1.y, a1.z, a1.w, bb.x, bb.y);
        }
        __syncthreads();
    }

    const float scale = (mb < 2) ? 0.125f * 1.4426950408889634f : 1.0f;
    const bool v_half = (mb >= 4);
#pragma unroll
    for (int t = 0; t < 2; t++) {
        int o_l = wm * 32 + t * 16 + gr;
        float bi0 = bias[mb * 128 + o_l];
        float bi1 = bias[mb * 128 + o_l + 8];
#pragma unroll
        for (int u_ = 0; u_ < 8; u_++) {
            int n_l = wn * 64 + u_ * 8 + 2 * tg;
            float v00 = (acc[t][u_][0] + bi0) * scale, v01 = (acc[t][u_][1] + bi0) * scale;
            float v10 = (acc[t][u_][2] + bi1) * scale, v11 = (acc[t][u_][3] + bi1) * scale;
            uint32_t w0 = v_half ? ph2(v00, v01) : pbf2(v00, v01);
            uint32_t w1 = v_half ? ph2(v10, v11) : pbf2(v10, v11);
            *(uint32_t*)&Ost[o_l * 130 + n_l] = w0;
            *(uint32_t*)&Ost[(o_l + 8) * 130 + n_l] = w1;
        }
    }
    __syncthreads();

    if (mb < 2) {
#pragma unroll
        for (int p = 0; p < 32; p++) {
            int idx = tid + p * 256;
            int n = idx >> 6;
            int ho = (idx >> 5) & 1;
            int cw = idx & 31;
            unsigned short lo = Ost[(ho * 64 + 2 * cw) * 130 + n];
            unsigned short hi = Ost[(ho * 64 + 2 * cw + 1) * 130 + n];
            uint32_t val = (uint32_t)lo | ((uint32_t)hi << 16);
            int bh = b * 4 + mb * 2 + ho;
            ((uint32_t*)g_qb)[((size_t)bh * 4096 + n0 + n) * 32 + cw] = val;
        }
    } else if (mb < 4) {
#pragma unroll
        for (int p = 0; p < 8; p++) {
            int e = tid + p * 256;
            int ln = e & 31, sp = (e >> 5) & 1, kt = (e >> 6) & 15, ho = e >> 10;
            int egr = ln >> 2, etg = ln & 3;
            int n = kt * 8 + egr;
            uint4 r;
            {
                int c0 = ho * 64 + (2 * sp) * 16 + 2 * etg;
                r.x = (uint32_t)Ost[c0 * 130 + n] | ((uint32_t)Ost[(c0 + 1) * 130 + n] << 16);
                r.y = (uint32_t)Ost[(c0 + 8) * 130 + n] | ((uint32_t)Ost[(c0 + 9) * 130 + n] << 16);
            }
            {
                int c0 = ho * 64 + (2 * sp + 1) * 16 + 2 * etg;
                r.z = (uint32_t)Ost[c0 * 130 + n] | ((uint32_t)Ost[(c0 + 1) * 130 + n] << 16);
                r.w = (uint32_t)Ost[(c0 + 8) * 130 + n] | ((uint32_t)Ost[(c0 + 9) * 130 + n] << 16);
            }
            int bh = b * 4 + (mb & 1) * 2 + ho;
            g_kf4[(((size_t)bh * 512 + (n0 >> 3) + kt) * 2 + sp) * 32 + ln] = r;
        }
    } else {
        int chv = blockIdx.x;
#pragma unroll
        for (int p = 0; p < 8; p++) {
            int e = tid + p * 256;
            int ln = e & 31, sp = (e >> 5) & 3, ct = (e >> 7) & 7, ho = e >> 10;
            int egr = ln >> 2, etg = ln & 3;
            int c = ho * 64 + ct * 8 + egr;
            uint4 r;
            {
                int nn = (2 * sp) * 16 + 2 * etg;
                r.x = *(uint32_t*)&Ost[c * 130 + nn];
                r.y = *(uint32_t*)&Ost[c * 130 + nn + 8];
            }
            {
                int nn = (2 * sp + 1) * 16 + 2 * etg;
                r.z = *(uint32_t*)&Ost[c * 130 + nn];
                r.w = *(uint32_t*)&Ost[c * 130 + nn + 8];
            }
            int bh = b * 4 + (mb - 4) * 2 + ho;
            g_vf4[((((size_t)bh * 32 + chv) * 8 + ct) * 4 + sp) * 32 + ln] = r;
        }
    }
}

// ---------------- Proj GEMM (bf16 mma, bf16 ao input) + bias + residual ----------
__global__ void __launch_bounds__(256) gemm_proj(const float* __restrict__ W,
                                                 const float* __restrict__ bias,
                                                 const float* __restrict__ resid,
                                                 float* __restrict__ outp) {
    __shared__ uint4 Af[8 * 32];
    __shared__ uint2 Bf[16 * 32];
    const int tid = threadIdx.x, wid = tid >> 5, lane = tid & 31;
    const int gr = lane >> 2, tg = lane & 3;
    const int n0 = blockIdx.x * 128, mb = blockIdx.y, b = blockIdx.z;
    const int wm = wid & 3, wn = wid >> 2;

    float acc[2][8][4] = {};
    const float* Abase = W + (size_t)(mb * 128) * 256;

    for (int k0 = 0; k0 < 256; k0 += 16) {
        {
            const float* ap = Abase + (size_t)(wid * 16 + gr) * 256 + k0 + 2 * tg;
            float2 w00 = *(const float2*)ap;
            float2 w10 = *(const float2*)(ap + 8 * 256);
            float2 w01 = *(const float2*)(ap + 8);
            float2 w11 = *(const float2*)(ap + 8 * 256 + 8);
            uint4 u;
            u.x = pbf2(w00.x, w00.y);
            u.y = pbf2(w10.x, w10.y);
            u.z = pbf2(w01.x, w01.y);
            u.w = pbf2(w11.x, w11.y);
            Af[wid * 32 + lane] = u;
        }
#pragma unroll
        for (int i = 0; i < 2; i++) {
            int u_ = wid * 2 + i;
            int n = n0 + u_ * 8 + gr;
            int c0 = k0 + 2 * tg;
            const unsigned short* xp =
                (const unsigned short*)(g_ao + ((size_t)(b * 256 + c0)) * 4096 + n);
            uint2 v;
            v.x = (uint32_t)xp[0] | ((uint32_t)xp[4096] << 16);
            v.y = (uint32_t)xp[8 * 4096] | ((uint32_t)xp[9 * 4096] << 16);
            Bf[u_ * 32 + lane] = v;
        }
        __syncthreads();
        uint4 a0 = Af[(wm * 2 + 0) * 32 + lane];
        uint4 a1 = Af[(wm * 2 + 1) * 32 + lane];
#pragma unroll
        for (int u_ = 0; u_ < 8; u_++) {
            uint2 bb = Bf[(wn * 8 + u_) * 32 + lane];
            mma_bf16(acc[0][u_], a0.x, a0.y, a0.z, a0.w, bb.x, bb.y);
            mma_bf16(acc[1][u_], a1.x, a1.y, a1.z, a1.w, bb.x, bb.y);
        }
        __syncthreads();
    }

#pragma unroll
    for (int t = 0; t < 2; t++) {
        int o = mb * 128 + wm * 32 + t * 16 + gr;
        float bi0 = bias[o], bi1 = bias[o + 8];
#pragma unroll
        for (int u_ = 0; u_ < 8; u_++) {
            size_t off = ((size_t)(b * 256 + o)) * 4096 + n0 + wn * 64 + u_ * 8 + 2 * tg;
            float2 r0 = *(const float2*)(resid + off);
            float2 o0;
            o0.x = acc[t][u_][0] + bi0 + r0.x;
            o0.y = acc[t][u_][1] + bi0 + r0.y;
            *(float2*)(outp + off) = o0;
            size_t off8 = off + 8 * 4096;
            float2 r1 = *(const float2*)(resid + off8);
            float2 o1;
            o1.x = acc[t][u_][2] + bi1 + r1.x;
            o1.y = acc[t][u_][3] + bi1 + r1.y;
            *(float2*)(outp + off8) = o1;
        }
    }
}

// ---------------- flash attention: R11 mainloop (ones-MMA rowsum), bf16 epilogue --
// grid (32 q-tiles, 16 bh), 128 thr = 4 warps x 32 q rows.
// smem: 3 stages x (K 16KB | V 16KB) = 96KB.
#define ATT_SMEM 98304
#define ONE2 0x3C003C00u

__global__ void __launch_bounds__(128, 2) attn_mma() {
    extern __shared__ char smc[];
    uint32_t sbase;
    asm("{ .reg .u64 t; cvta.to.shared.u64 t, %1; cvt.u32.u64 %0, t; }" : "=r"(sbase) : "l"(smc));

    const int tid = threadIdx.x, wid = tid >> 5, lane = tid & 31;
    const int gr = lane >> 2, tg = lane & 3;
    const int qt = blockIdx.x, bh = blockIdx.y;
    const int b = bh >> 2, hh = bh & 3;
    const int w32 = wid * 32;

    const __nv_bfloat16* qg = g_qb + ((size_t)bh * 4096 + qt * 128) * 64;
    const uint4* kfg = g_kf4 + (size_t)bh * 32768;
    const uint4* vfg = g_vf4 + (size_t)bh * 32768;

    uint32_t qa[2][4][4];
#pragma unroll
    for (int at = 0; at < 2; at++) {
#pragma unroll
        for (int s = 0; s < 4; s++) {
            const __nv_bfloat16* base = qg + (size_t)(w32 + at * 16 + gr) * 64 + s * 16 + 2 * tg;
            qa[at][s][0] = *(const uint32_t*)(base);
            qa[at][s][1] = *(const uint32_t*)(base + 8 * 64);
            qa[at][s][2] = *(const uint32_t*)(base + 8);
            qa[at][s][3] = *(const uint32_t*)(base + 8 * 64 + 8);
        }
    }

    float oacc[2][8][4] = {};
    float rsacc[2][4] = {};

#define PREFETCH(ch) do {                                                     \
        int _c = (ch);                                                       \
        if (_c < 32) {                                                       \
            uint32_t _sk = sbase + (uint32_t)(_c % 3) * 32768;               \
            const uint4* _gk = kfg + (size_t)_c * 1024;                      \
            const uint4* _gv = vfg + (size_t)_c * 1024;                      \
            _Pragma("unroll")                                                \
            for (int _i = 0; _i < 8; _i++)                                   \
                cp16(_sk + (tid + _i * 128) * 16, _gk + tid + _i * 128);     \
            _Pragma("unroll")                                                \
            for (int _i = 0; _i < 8; _i++)                                   \
                cp16(_sk + 16384 + (tid + _i * 128) * 16, _gv + tid + _i * 128); \
        }                                                                    \
        CP_COMMIT();                                                         \
    } while (0)

#define S_CALC(dst, g) do {                                                  \
        _Pragma("unroll")                                                    \
        for (int _u = 0; _u < 4; _u++) {                                     \
            uint4 _k0 = Kf4[(((g) * 4 + _u) * 2 + 0) * 32 + lane];           \
            uint4 _k1 = Kf4[(((g) * 4 + _u) * 2 + 1) * 32 + lane];           \
            _Pragma("unroll")                                                \
            for (int _at = 0; _at < 2; _at++) {                              \
                dst[_at][_u][0] = 0.f; dst[_at][_u][1] = 0.f;                \
                dst[_at][_u][2] = 0.f; dst[_at][_u][3] = 0.f;                \
                mma_bf16(dst[_at][_u], qa[_at][0][0], qa[_at][0][1], qa[_at][0][2], qa[_at][0][3], _k0.x, _k0.y); \
                mma_bf16(dst[_at][_u], qa[_at][1][0], qa[_at][1][1], qa[_at][1][2], qa[_at][1][3], _k0.z, _k0.w); \
                mma_bf16(dst[_at][_u], qa[_at][2][0], qa[_at][2][1], qa[_at][2][2], qa[_at][2][3], _k1.x, _k1.y); \
                mma_bf16(dst[_at][_u], qa[_at][3][0], qa[_at][3][1], qa[_at][3][2], qa[_at][3][3], _k1.z, _k1.w); \
            }                                                                \
        }                                                                    \
    } while (0)

#define E_CALC(pdst, src) do {                                               \
        _Pragma("unroll")                                                    \
        for (int _at = 0; _at < 2; _at++) {                                  \
            _Pragma("unroll")                                                \
            for (int _u = 0; _u < 4; _u++) {                                 \
                pdst[_at][_u][0] = ex2h2(ph2(src[_at][_u][0], src[_at][_u][1])); \
                pdst[_at][_u][1] = ex2h2(ph2(src[_at][_u][2], src[_at][_u][3])); \
            }                                                                \
        }                                                                    \
    } while (0)

#define V_CALC(g, psrc) do {                                                 \
        _Pragma("unroll")                                                    \
        for (int _ct = 0; _ct < 8; _ct++) {                                  \
            uint4 _v = Vf4[(_ct * 4 + (g)) * 32 + lane];                     \
            _Pragma("unroll")                                                \
            for (int _at = 0; _at < 2; _at++) {                              \
                mma_f16(oacc[_at][_ct], psrc[_at][0][0], psrc[_at][0][1],    \
                        psrc[_at][1][0], psrc[_at][1][1], _v.x, _v.y);       \
                mma_f16(oacc[_at][_ct], psrc[_at][2][0], psrc[_at][2][1],    \
                        psrc[_at][3][0], psrc[_at][3][1], _v.z, _v.w);       \
            }                                                                \
        }                                                                    \
        _Pragma("unroll")                                                    \
        for (int _at = 0; _at < 2; _at++) {                                  \
            mma_f16(rsacc[_at], psrc[_at][0][0], psrc[_at][0][1],            \
                    psrc[_at][1][0], psrc[_at][1][1], ONE2, ONE2);           \
            mma_f16(rsacc[_at], psrc[_at][2][0], psrc[_at][2][1],            \
                    psrc[_at][3][0], psrc[_at][3][1], ONE2, ONE2);           \
        }                                                                    \
    } while (0)

    PREFETCH(0);
    PREFETCH(1);

    for (int ch = 0; ch < 32; ch++) {
        CP_WAIT1();
        __syncthreads();
        PREFETCH(ch + 2);

        const uint4* Kf4 = (const uint4*)(smc + (ch % 3) * 32768);
        const uint4* Vf4 = (const uint4*)(smc + (ch % 3) * 32768 + 16384);

        float sA[2][4][4], sB[2][4][4];
        uint32_t pA[2][4][2], pB[2][4][2];

        S_CALC(sA, 0);
        E_CALC(pA, sA);
        S_CALC(sB, 1);
        V_CALC(0, pA);
        E_CALC(pB, sB);
        S_CALC(sA, 2);
        V_CALC(1, pB);
        E_CALC(pA, sA);
        S_CALC(sB, 3);
        V_CALC(2, pA);
        E_CALC(pB, sB);
        V_CALC(3, pB);
    }
#undef PREFETCH
#undef S_CALC
#undef E_CALC
#undef V_CALC

    // rowsums: every lane of rsacc holds the full row sum (ones columns)
    float ri[2][2];
#pragma unroll
    for (int at = 0; at < 2; at++) {
        ri[at][0] = 1.0f / rsacc[at][0];
        ri[at][1] = 1.0f / rsacc[at][2];
    }

    // stage O as bf16 [64 c][136 pitch], then coalesced uint4 writes
    unsigned short* Os = (unsigned short*)smc;
    __syncthreads();
#pragma unroll
    for (int at = 0; at < 2; at++) {
#pragma unroll
        for (int ct = 0; ct < 8; ct++) {
            int c = ct * 8 + 2 * tg;
            int q0 = w32 + at * 16 + gr;
            __nv_bfloat16 b0 = __float2bfloat16(oacc[at][ct][0] * ri[at][0]);
            __nv_bfloat16 b1 = __float2bfloat16(oacc[at][ct][1] * ri[at][0]);
            __nv_bfloat16 b2 = __float2bfloat16(oacc[at][ct][2] * ri[at][1]);
            __nv_bfloat16 b3 = __float2bfloat16(oacc[at][ct][3] * ri[at][1]);
            Os[c * 136 + q0] = *(unsigned short*)&b0;
            Os[(c + 1) * 136 + q0] = *(unsigned short*)&b1;
            Os[c * 136 + q0 + 8] = *(unsigned short*)&b2;
            Os[(c + 1) * 136 + q0 + 8] = *(unsigned short*)&b3;
        }
    }
    __syncthreads();

    unsigned short* dst = (unsigned short*)(g_ao + ((size_t)(b * 256 + hh * 64)) * 4096 + qt * 128);
#pragma unroll
    for (int p = 0; p < 8; p++) {
        int idx = tid + p * 128;         // 1024 uint4 = 64 rows x 16
        int c = idx >> 4, q8 = idx & 15;
        uint4 v = *(const uint4*)&Os[c * 136 + q8 * 8];
        *(uint4*)&dst[(size_t)c * 4096 + q8 * 8] = v;
    }
}

// ---------------- launch ----------------
extern "C" void kernel_launch(void* const* d_in, const int* in_sizes, int n_in,
                              void* d_out, int out_size) {
    (void)in_sizes; (void)n_in; (void)out_size;
    const float* x      = (const float*)d_in[0];
    const float* norm_w = (const float*)d_in[1];
    const float* norm_b = (const float*)d_in[2];
    const float* qkv_w  = (const float*)d_in[3];
    const float* qkv_b  = (const float*)d_in[4];
    const float* proj_w = (const float*)d_in[5];
    const float* proj_b = (const float*)d_in[6];
    float* out = (float*)d_out;

    cudaFuncSetAttribute(attn_mma, cudaFuncAttributeMaxDynamicSharedMemorySize, ATT_SMEM);

    gn_partial<<<dim3(32, 16), 256>>>(x);

    gemm_qkv<<<dim3(32, 6, 4), 256, QKV_SMEM>>>(qkv_w, x, qkv_b, norm_w, norm_b);

    attn_mma<<<dim3(32, 16), 128, ATT_SMEM>>>();

    gemm_proj<<<dim3(32, 2, 4), 256>>>(proj_w, proj_b, x, out);
}

// round 14
// speedup vs baseline: 1.0925x; 1.0217x over previous
#include <cuda_runtime.h>
#include <cuda_bf16.h>
#include <cuda_fp16.h>
#include <math.h>
#include <cstdint>

#define EPSV 1e-5f

// ---------------- scratch (device globals; allocation-free) ----------------
__device__ __nv_bfloat16 g_qb[16 * 4096 * 64];   // q: [bh][n][c], pre-scaled 0.125*log2e
__device__ uint4 g_kf4[16 * 512 * 2 * 32];       // K frags (bf16): [bh][kt][sp][lane]
__device__ uint4 g_vf4[16 * 32 * 8 * 4 * 32];    // V frags (fp16): [bh][chunk][ct][sp][lane]
__device__ uint2 g_aof[4 * 16 * 512 * 32];       // attention out, proj-B-frag order:
                                                 // [b][kg 0..15][ntile 0..511][lane] bf16 pairs
__device__ float g_part[32 * 16 * 2];

// ======================= helpers =======================
__device__ __forceinline__ uint32_t pbf2(float lo, float hi) {
    __nv_bfloat162 t = __floats2bfloat162_rn(lo, hi);
    return *(uint32_t*)&t;
}
__device__ __forceinline__ uint32_t ph2(float lo, float hi) {
    __half2 t = __floats2half2_rn(lo, hi);
    return *(uint32_t*)&t;
}
__device__ __forceinline__ uint32_t ex2h2(uint32_t h2) {
    uint32_t r;
    asm("ex2.approx.f16x2 %0, %1;" : "=r"(r) : "r"(h2));
    return r;
}
__device__ __forceinline__ void mma_bf16(float d[4], const uint32_t a0, const uint32_t a1,
                                         const uint32_t a2, const uint32_t a3,
                                         const uint32_t b0, const uint32_t b1) {
    asm volatile("mma.sync.aligned.m16n8k16.row.col.f32.bf16.bf16.f32 "
                 "{%0,%1,%2,%3}, {%4,%5,%6,%7}, {%8,%9}, {%0,%1,%2,%3};"
                 : "+f"(d[0]), "+f"(d[1]), "+f"(d[2]), "+f"(d[3])
                 : "r"(a0), "r"(a1), "r"(a2), "r"(a3), "r"(b0), "r"(b1));
}
__device__ __forceinline__ void mma_f16(float d[4], const uint32_t a0, const uint32_t a1,
                                        const uint32_t a2, const uint32_t a3,
                                        const uint32_t b0, const uint32_t b1) {
    asm volatile("mma.sync.aligned.m16n8k16.row.col.f32.f16.f16.f32 "
                 "{%0,%1,%2,%3}, {%4,%5,%6,%7}, {%8,%9}, {%0,%1,%2,%3};"
                 : "+f"(d[0]), "+f"(d[1]), "+f"(d[2]), "+f"(d[3])
                 : "r"(a0), "r"(a1), "r"(a2), "r"(a3), "r"(b0), "r"(b1));
}
__device__ __forceinline__ void cp16(uint32_t saddr, const void* gaddr) {
    asm volatile("cp.async.cg.shared.global [%0], [%1], 16;" :: "r"(saddr), "l"(gaddr));
}
#define CP_COMMIT() asm volatile("cp.async.commit_group;" ::: "memory")
#define CP_WAIT1()  asm volatile("cp.async.wait_group 1;" ::: "memory")

// ---------------- GroupNorm partial stats ----------------
__global__ void gn_partial(const float* __restrict__ x) {
    int bg = blockIdx.x;
    int chunk = blockIdx.y;
    const float4* p = (const float4*)(x + (size_t)bg * 32 * 4096 + (size_t)chunk * 8192);
    float s = 0.f, q = 0.f;
#pragma unroll
    for (int i = 0; i < 8; i++) {
        float4 v = p[threadIdx.x + i * 256];
        s += v.x + v.y + v.z + v.w;
        q += v.x * v.x + v.y * v.y + v.z * v.z + v.w * v.w;
    }
    __shared__ float ss[256], sq[256];
    ss[threadIdx.x] = s; sq[threadIdx.x] = q;
    __syncthreads();
    for (int o = 128; o > 0; o >>= 1) {
        if (threadIdx.x < o) {
            ss[threadIdx.x] += ss[threadIdx.x + o];
            sq[threadIdx.x] += sq[threadIdx.x + o];
        }
        __syncthreads();
    }
    if (threadIdx.x == 0) {
        g_part[(bg * 16 + chunk) * 2 + 0] = ss[0];
        g_part[(bg * 16 + chunk) * 2 + 1] = sq[0];
    }
}

// ---------------- QKV GEMM (bf16 m16n8k16 mma, GN finalize+apply fused) -----------
#define QKV_SMEM 35328

__global__ void __launch_bounds__(256) gemm_qkv(const float* __restrict__ W,
                                                const float* __restrict__ x,
                                                const float* __restrict__ bias,
                                                const float* __restrict__ nw,
                                                const float* __restrict__ nbv) {
    extern __shared__ char sm[];
    uint4* Af = (uint4*)sm;
    uint2* Bf = (uint2*)(sm + 4096);
    unsigned short* Ost = (unsigned short*)sm;      // [128][130] 16-bit overlay
    float* sc = (float*)(sm + 33280);
    float* sh = (float*)(sm + 34304);

    const int tid = threadIdx.x, wid = tid >> 5, lane = tid & 31;
    const int gr = lane >> 2, tg = lane & 3;
    const int n0 = blockIdx.x * 128, mb = blockIdx.y, b = blockIdx.z;
    const int wm = wid & 3, wn = wid >> 2;

    {
        int c = tid;
        int bg = b * 8 + (c >> 5);
        float s_ = 0.f, q_ = 0.f;
#pragma unroll
        for (int i = 0; i < 16; i++) {
            s_ += g_part[(bg * 16 + i) * 2 + 0];
            q_ += g_part[(bg * 16 + i) * 2 + 1];
        }
        const float inv = 1.0f / 131072.0f;
        float mean = s_ * inv;
        float var = q_ * inv - mean * mean;
        float rstd = rsqrtf(var + EPSV);
        float s = rstd * nw[c];
        sc[c] = s;
        sh[c] = nbv[c] - mean * s;
    }
    __syncthreads();

    float acc[2][8][4] = {};
    const float* Abase = W + (size_t)(mb * 128) * 256;

    for (int k0 = 0; k0 < 256; k0 += 16) {
        {
            const float* ap = Abase + (size_t)(wid * 16 + gr) * 256 + k0 + 2 * tg;
            float2 w00 = *(const float2*)ap;
            float2 w10 = *(const float2*)(ap + 8 * 256);
            float2 w01 = *(const float2*)(ap + 8);
            float2 w11 = *(const float2*)(ap + 8 * 256 + 8);
            uint4 u;
            u.x = pbf2(w00.x, w00.y);
            u.y = pbf2(w10.x, w10.y);
            u.z = pbf2(w01.x, w01.y);
            u.w = pbf2(w11.x, w11.y);
            Af[wid * 32 + lane] = u;
        }
#pragma unroll
        for (int i = 0; i < 2; i++) {
            int u_ = wid * 2 + i;
            int n = n0 + u_ * 8 + gr;
            int c0 = k0 + 2 * tg;
            const float* xp = x + ((size_t)(b * 256 + c0)) * 4096 + n;
            float h00 = xp[0] * sc[c0] + sh[c0];
            float h01 = xp[4096] * sc[c0 + 1] + sh[c0 + 1];
            float h10 = xp[8 * 4096] * sc[c0 + 8] + sh[c0 + 8];
            float h11 = xp[9 * 4096] * sc[c0 + 9] + sh[c0 + 9];
            uint2 v;
            v.x = pbf2(h00, h01);
            v.y = pbf2(h10, h11);
            Bf[u_ * 32 + lane] = v;
        }
        __syncthreads();
        uint4 a0 = Af[(wm * 2 + 0) * 32 + lane];
        uint4 a1 = Af[(wm * 2 + 1) * 32 + lane];
#pragma unroll
        for (int u_ = 0; u_ < 8; u_++) {
            uint2 bb = Bf[(wn * 8 + u_) * 32 + lane];
            mma_bf16(acc[0][u_], a0.x, a0.y, a0.z, a0.w, bb.x, bb.y);
            mma_bf16(acc[1][u_], a1.x, a1.y, a1.z, a1.w, bb.x, bb.y);
        }
        __syncthreads();
    }

    const float scale = (mb < 2) ? 0.125f * 1.4426950408889634f : 1.0f;
    const bool v_half = (mb >= 4);
#pragma unroll
    for (int t = 0; t < 2; t++) {
        int o_l = wm * 32 + t * 16 + gr;
        float bi0 = bias[mb * 128 + o_l];
        float bi1 = bias[mb * 128 + o_l + 8];
#pragma unroll
        for (int u_ = 0; u_ < 8; u_++) {
            int n_l = wn * 64 + u_ * 8 + 2 * tg;
            float v00 = (acc[t][u_][0] + bi0) * scale, v01 = (acc[t][u_][1] + bi0) * scale;
            float v10 = (acc[t][u_][2] + bi1) * scale, v11 = (acc[t][u_][3] + bi1) * scale;
            uint32_t w0 = v_half ? ph2(v00, v01) : pbf2(v00, v01);
            uint32_t w1 = v_half ? ph2(v10, v11) : pbf2(v10, v11);
            *(uint32_t*)&Ost[o_l * 130 + n_l] = w0;
            *(uint32_t*)&Ost[(o_l + 8) * 130 + n_l] = w1;
        }
    }
    __syncthreads();

    if (mb < 2) {
#pragma unroll
        for (int p = 0; p < 32; p++) {
            int idx = tid + p * 256;
            int n = idx >> 6;
            int ho = (idx >> 5) & 1;
            int cw = idx & 31;
            unsigned short lo = Ost[(ho * 64 + 2 * cw) * 130 + n];
            unsigned short hi = Ost[(ho * 64 + 2 * cw + 1) * 130 + n];
            uint32_t val = (uint32_t)lo | ((uint32_t)hi << 16);
            int bh = b * 4 + mb * 2 + ho;
            ((uint32_t*)g_qb)[((size_t)bh * 4096 + n0 + n) * 32 + cw] = val;
        }
    } else if (mb < 4) {
#pragma unroll
        for (int p = 0; p < 8; p++) {
            int e = tid + p * 256;
            int ln = e & 31, sp = (e >> 5) & 1, kt = (e >> 6) & 15, ho = e >> 10;
            int egr = ln >> 2, etg = ln & 3;
            int n = kt * 8 + egr;
            uint4 r;
            {
                int c0 = ho * 64 + (2 * sp) * 16 + 2 * etg;
                r.x = (uint32_t)Ost[c0 * 130 + n] | ((uint32_t)Ost[(c0 + 1) * 130 + n] << 16);
                r.y = (uint32_t)Ost[(c0 + 8) * 130 + n] | ((uint32_t)Ost[(c0 + 9) * 130 + n] << 16);
            }
            {
                int c0 = ho * 64 + (2 * sp + 1) * 16 + 2 * etg;
                r.z = (uint32_t)Ost[c0 * 130 + n] | ((uint32_t)Ost[(c0 + 1) * 130 + n] << 16);
                r.w = (uint32_t)Ost[(c0 + 8) * 130 + n] | ((uint32_t)Ost[(c0 + 9) * 130 + n] << 16);
            }
            int bh = b * 4 + (mb & 1) * 2 + ho;
            g_kf4[(((size_t)bh * 512 + (n0 >> 3) + kt) * 2 + sp) * 32 + ln] = r;
        }
    } else {
        int chv = blockIdx.x;
#pragma unroll
        for (int p = 0; p < 8; p++) {
            int e = tid + p * 256;
            int ln = e & 31, sp = (e >> 5) & 3, ct = (e >> 7) & 7, ho = e >> 10;
            int egr = ln >> 2, etg = ln & 3;
            int c = ho * 64 + ct * 8 + egr;
            uint4 r;
            {
                int nn = (2 * sp) * 16 + 2 * etg;
                r.x = *(uint32_t*)&Ost[c * 130 + nn];
                r.y = *(uint32_t*)&Ost[c * 130 + nn + 8];
            }
            {
                int nn = (2 * sp + 1) * 16 + 2 * etg;
                r.z = *(uint32_t*)&Ost[c * 130 + nn];
                r.w = *(uint32_t*)&Ost[c * 130 + nn + 8];
            }
            int bh = b * 4 + (mb - 4) * 2 + ho;
            g_vf4[((((size_t)bh * 32 + chv) * 8 + ct) * 4 + sp) * 32 + ln] = r;
        }
    }
}

// ---------------- Proj GEMM (bf16 mma, fragment-ordered ao) + bias + residual -----
__global__ void __launch_bounds__(256) gemm_proj(const float* __restrict__ W,
                                                 const float* __restrict__ bias,
                                                 const float* __restrict__ resid,
                                                 float* __restrict__ outp) {
    __shared__ uint4 Af[8 * 32];
    __shared__ uint2 Bf[16 * 32];
    const int tid = threadIdx.x, wid = tid >> 5, lane = tid & 31;
    const int gr = lane >> 2, tg = lane & 3;
    const int n0 = blockIdx.x * 128, mb = blockIdx.y, b = blockIdx.z;
    const int wm = wid & 3, wn = wid >> 2;

    float acc[2][8][4] = {};
    const float* Abase = W + (size_t)(mb * 128) * 256;

    for (int k0 = 0; k0 < 256; k0 += 16) {
        {
            const float* ap = Abase + (size_t)(wid * 16 + gr) * 256 + k0 + 2 * tg;
            float2 w00 = *(const float2*)ap;
            float2 w10 = *(const float2*)(ap + 8 * 256);
            float2 w01 = *(const float2*)(ap + 8);
            float2 w11 = *(const float2*)(ap + 8 * 256 + 8);
            uint4 u;
            u.x = pbf2(w00.x, w00.y);
            u.y = pbf2(w10.x, w10.y);
            u.z = pbf2(w01.x, w01.y);
            u.w = pbf2(w11.x, w11.y);
            Af[wid * 32 + lane] = u;
        }
        // B frags: ONE coalesced uint2 load per fragment (fragment-ordered g_aof)
        {
            const uint2* src = g_aof + (((size_t)(b * 16 + (k0 >> 4)) * 512 + (n0 >> 3)) * 32);
#pragma unroll
            for (int i = 0; i < 2; i++) {
                int u_ = wid * 2 + i;
                Bf[u_ * 32 + lane] = src[u_ * 32 + lane];
            }
        }
        __syncthreads();
        uint4 a0 = Af[(wm * 2 + 0) * 32 + lane];
        uint4 a1 = Af[(wm * 2 + 1) * 32 + lane];
#pragma unroll
        for (int u_ = 0; u_ < 8; u_++) {
            uint2 bb = Bf[(wn * 8 + u_) * 32 + lane];
            mma_bf16(acc[0][u_], a0.x, a0.y, a0.z, a0.w, bb.x, bb.y);
            mma_bf16(acc[1][u_], a1.x, a1.y, a1.z, a1.w, bb.x, bb.y);
        }
        __syncthreads();
    }

#pragma unroll
    for (int t = 0; t < 2; t++) {
        int o = mb * 128 + wm * 32 + t * 16 + gr;
        float bi0 = bias[o], bi1 = bias[o + 8];
#pragma unroll
        for (int u_ = 0; u_ < 8; u_++) {
            size_t off = ((size_t)(b * 256 + o)) * 4096 + n0 + wn * 64 + u_ * 8 + 2 * tg;
            float2 r0 = *(const float2*)(resid + off);
            float2 o0;
            o0.x = acc[t][u_][0] + bi0 + r0.x;
            o0.y = acc[t][u_][1] + bi0 + r0.y;
            *(float2*)(outp + off) = o0;
            size_t off8 = off + 8 * 4096;
            float2 r1 = *(const float2*)(resid + off8);
            float2 o1;
            o1.x = acc[t][u_][2] + bi1 + r1.x;
            o1.y = acc[t][u_][3] + bi1 + r1.y;
            *(float2*)(outp + off8) = o1;
        }
    }
}

// ---------------- flash attention: R11 mainloop; fragment-ordered bf16 epilogue ---
// grid (32 q-tiles, 16 bh), 128 thr = 4 warps x 32 q rows.
// smem: 3 stages x (K 16KB | V 16KB) = 96KB.
// Epilogue writes O directly in proj's B-fragment layout (coalesced uint2).
#define ATT_SMEM 98304
#define ONE2 0x3C003C00u

__global__ void __launch_bounds__(128, 2) attn_mma() {
    extern __shared__ char smc[];
    uint32_t sbase;
    asm("{ .reg .u64 t; cvta.to.shared.u64 t, %1; cvt.u32.u64 %0, t; }" : "=r"(sbase) : "l"(smc));

    const int tid = threadIdx.x, wid = tid >> 5, lane = tid & 31;
    const int gr = lane >> 2, tg = lane & 3;
    const int qt = blockIdx.x, bh = blockIdx.y;
    const int b = bh >> 2, hh = bh & 3;
    const int w32 = wid * 32;

    const __nv_bfloat16* qg = g_qb + ((size_t)bh * 4096 + qt * 128) * 64;
    const uint4* kfg = g_kf4 + (size_t)bh * 32768;
    const uint4* vfg = g_vf4 + (size_t)bh * 32768;

    uint32_t qa[2][4][4];
#pragma unroll
    for (int at = 0; at < 2; at++) {
#pragma unroll
        for (int s = 0; s < 4; s++) {
            const __nv_bfloat16* base = qg + (size_t)(w32 + at * 16 + gr) * 64 + s * 16 + 2 * tg;
            qa[at][s][0] = *(const uint32_t*)(base);
            qa[at][s][1] = *(const uint32_t*)(base + 8 * 64);
            qa[at][s][2] = *(const uint32_t*)(base + 8);
            qa[at][s][3] = *(const uint32_t*)(base + 8 * 64 + 8);
        }
    }

    float oacc[2][8][4] = {};
    float rsacc[2][4] = {};

#define PREFETCH(ch) do {                                                     \
        int _c = (ch);                                                       \
        if (_c < 32) {                                                       \
            uint32_t _sk = sbase + (uint32_t)(_c % 3) * 32768;               \
            const uint4* _gk = kfg + (size_t)_c * 1024;                      \
            const uint4* _gv = vfg + (size_t)_c * 1024;                      \
            _Pragma("unroll")                                                \
            for (int _i = 0; _i < 8; _i++)                                   \
                cp16(_sk + (tid + _i * 128) * 16, _gk + tid + _i * 128);     \
            _Pragma("unroll")                                                \
            for (int _i = 0; _i < 8; _i++)                                   \
                cp16(_sk + 16384 + (tid + _i * 128) * 16, _gv + tid + _i * 128); \
        }                                                                    \
        CP_COMMIT();                                                         \
    } while (0)

#define S_CALC(dst, g) do {                                                  \
        _Pragma("unroll")                                                    \
        for (int _u = 0; _u < 4; _u++) {                                     \
            uint4 _k0 = Kf4[(((g) * 4 + _u) * 2 + 0) * 32 + lane];           \
            uint4 _k1 = Kf4[(((g) * 4 + _u) * 2 + 1) * 32 + lane];           \
            _Pragma("unroll")                                                \
            for (int _at = 0; _at < 2; _at++) {                              \
                dst[_at][_u][0] = 0.f; dst[_at][_u][1] = 0.f;                \
                dst[_at][_u][2] = 0.f; dst[_at][_u][3] = 0.f;                \
                mma_bf16(dst[_at][_u], qa[_at][0][0], qa[_at][0][1], qa[_at][0][2], qa[_at][0][3], _k0.x, _k0.y); \
                mma_bf16(dst[_at][_u], qa[_at][1][0], qa[_at][1][1], qa[_at][1][2], qa[_at][1][3], _k0.z, _k0.w); \
                mma_bf16(dst[_at][_u], qa[_at][2][0], qa[_at][2][1], qa[_at][2][2], qa[_at][2][3], _k1.x, _k1.y); \
                mma_bf16(dst[_at][_u], qa[_at][3][0], qa[_at][3][1], qa[_at][3][2], qa[_at][3][3], _k1.z, _k1.w); \
            }                                                                \
        }                                                                    \
    } while (0)

#define E_CALC(pdst, src) do {                                               \
        _Pragma("unroll")                                                    \
        for (int _at = 0; _at < 2; _at++) {                                  \
            _Pragma("unroll")                                                \
            for (int _u = 0; _u < 4; _u++) {                                 \
                pdst[_at][_u][0] = ex2h2(ph2(src[_at][_u][0], src[_at][_u][1])); \
                pdst[_at][_u][1] = ex2h2(ph2(src[_at][_u][2], src[_at][_u][3])); \
            }                                                                \
        }                                                                    \
    } while (0)

#define V_CALC(g, psrc) do {                                                 \
        _Pragma("unroll")                                                    \
        for (int _ct = 0; _ct < 8; _ct++) {                                  \
            uint4 _v = Vf4[(_ct * 4 + (g)) * 32 + lane];                     \
            _Pragma("unroll")                                                \
            for (int _at = 0; _at < 2; _at++) {                              \
                mma_f16(oacc[_at][_ct], psrc[_at][0][0], psrc[_at][0][1],    \
                        psrc[_at][1][0], psrc[_at][1][1], _v.x, _v.y);       \
                mma_f16(oacc[_at][_ct], psrc[_at][2][0], psrc[_at][2][1],    \
                        psrc[_at][3][0], psrc[_at][3][1], _v.z, _v.w);       \
            }                                                                \
        }                                                                    \
        _Pragma("unroll")                                                    \
        for (int _at = 0; _at < 2; _at++) {                                  \
            mma_f16(rsacc[_at], psrc[_at][0][0], psrc[_at][0][1],            \
                    psrc[_at][1][0], psrc[_at][1][1], ONE2, ONE2);           \
            mma_f16(rsacc[_at], psrc[_at][2][0], psrc[_at][2][1],            \
                    psrc[_at][3][0], psrc[_at][3][1], ONE2, ONE2);           \
        }                                                                    \
    } while (0)

    PREFETCH(0);
    PREFETCH(1);

    for (int ch = 0; ch < 32; ch++) {
        CP_WAIT1();
        __syncthreads();
        PREFETCH(ch + 2);

        const uint4* Kf4 = (const uint4*)(smc + (ch % 3) * 32768);
        const uint4* Vf4 = (const uint4*)(smc + (ch % 3) * 32768 + 16384);

        float sA[2][4][4], sB[2][4][4];
        uint32_t pA[2][4][2], pB[2][4][2];

        S_CALC(sA, 0);
        E_CALC(pA, sA);
        S_CALC(sB, 1);
        V_CALC(0, pA);
        E_CALC(pB, sB);
        S_CALC(sA, 2);
        V_CALC(1, pB);
        E_CALC(pA, sA);
        S_CALC(sB, 3);
        V_CALC(2, pA);
        E_CALC(pB, sB);
        V_CALC(3, pB);
    }
#undef PREFETCH
#undef S_CALC
#undef E_CALC
#undef V_CALC

    // rowsums: every lane of rsacc holds the full row sum (ones columns)
    float ri[2][2];
#pragma unroll
    for (int at = 0; at < 2; at++) {
        ri[at][0] = 1.0f / rsacc[at][0];
        ri[at][1] = 1.0f / rsacc[at][2];
    }

    // epilogue: write O directly in proj's B-fragment order (coalesced uint2).
    // thread (gr,tg): oacc[at][ct] pair (d0,d1) @ rows q0 -> ntile nt0;
    //                 (d2,d3) @ rows q0+8 -> ntile nt0+1.
    // kg = hh*4 + (ct>>1); ct even -> .x (c%16 = 2tg), ct odd -> .y (c%16 = 8+2tg).
#pragma unroll
    for (int at = 0; at < 2; at++) {
        int nt0 = qt * 16 + wid * 4 + at * 2;
#pragma unroll
        for (int kgl = 0; kgl < 4; kgl++) {
            int kg = hh * 4 + kgl;
            uint2 f0, f1;
            f0.x = pbf2(oacc[at][2 * kgl][0] * ri[at][0], oacc[at][2 * kgl][1] * ri[at][0]);
            f0.y = pbf2(oacc[at][2 * kgl + 1][0] * ri[at][0], oacc[at][2 * kgl + 1][1] * ri[at][0]);
            f1.x = pbf2(oacc[at][2 * kgl][2] * ri[at][1], oacc[at][2 * kgl][3] * ri[at][1]);
            f1.y = pbf2(oacc[at][2 * kgl + 1][2] * ri[at][1], oacc[at][2 * kgl + 1][3] * ri[at][1]);
            size_t base = ((size_t)(b * 16 + kg) * 512 + nt0) * 32 + lane;
            g_aof[base] = f0;
            g_aof[base + 32] = f1;
        }
    }
}

// ---------------- launch ----------------
extern "C" void kernel_launch(void* const* d_in, const int* in_sizes, int n_in,
                              void* d_out, int out_size) {
    (void)in_sizes; (void)n_in; (void)out_size;
    const float* x      = (const float*)d_in[0];
    const float* norm_w = (const float*)d_in[1];
    const float* norm_b = (const float*)d_in[2];
    const float* qkv_w  = (const float*)d_in[3];
    const float* qkv_b  = (const float*)d_in[4];
    const float* proj_w = (const float*)d_in[5];
    const float* proj_b = (const float*)d_in[6];
    float* out = (float*)d_out;

    cudaFuncSetAttribute(attn_mma, cudaFuncAttributeMaxDynamicSharedMemorySize, ATT_SMEM);

    gn_partial<<<dim3(32, 16), 256>>>(x);

    gemm_qkv<<<dim3(32, 6, 4), 256, QKV_SMEM>>>(qkv_w, x, qkv_b, norm_w, norm_b);

    attn_mma<<<dim3(32, 16), 128, ATT_SMEM>>>();

    gemm_proj<<<dim3(32, 2, 4), 256>>>(proj_w, proj_b, x, out);
}

// round 15
// speedup vs baseline: 1.1711x; 1.0720x over previous
#include <cuda_runtime.h>
#include <cuda_bf16.h>
#include <cuda_fp16.h>
#include <math.h>
#include <cstdint>

#define EPSV 1e-5f

// ---------------- scratch (device globals; allocation-free) ----------------
__device__ __nv_bfloat16 g_qb[16 * 4096 * 64];   // q: [bh][n][c], pre-scaled 0.125*log2e
__device__ uint4 g_kf4[16 * 512 * 2 * 32];       // K frags (bf16): [bh][kt][sp][lane]
__device__ uint4 g_vf4[16 * 32 * 8 * 4 * 32];    // V frags (fp16): [bh][chunk][ct][sp][lane]
__device__ uint2 g_aof[4 * 16 * 512 * 32];       // attention out, proj-B-frag order
__device__ uint4 g_wqf[6 * 16 * 8 * 32];         // qkv W, A-frag order [mb][ks][wid][lane]
__device__ uint4 g_wpf[2 * 16 * 8 * 32];         // proj W, A-frag order
__device__ float g_part[32 * 16 * 2];

// ======================= helpers =======================
__device__ __forceinline__ uint32_t pbf2(float lo, float hi) {
    __nv_bfloat162 t = __floats2bfloat162_rn(lo, hi);
    return *(uint32_t*)&t;
}
__device__ __forceinline__ uint32_t ph2(float lo, float hi) {
    __half2 t = __floats2half2_rn(lo, hi);
    return *(uint32_t*)&t;
}
__device__ __forceinline__ uint32_t ex2h2(uint32_t h2) {
    uint32_t r;
    asm("ex2.approx.f16x2 %0, %1;" : "=r"(r) : "r"(h2));
    return r;
}
__device__ __forceinline__ void mma_bf16(float d[4], const uint32_t a0, const uint32_t a1,
                                         const uint32_t a2, const uint32_t a3,
                                         const uint32_t b0, const uint32_t b1) {
    asm volatile("mma.sync.aligned.m16n8k16.row.col.f32.bf16.bf16.f32 "
                 "{%0,%1,%2,%3}, {%4,%5,%6,%7}, {%8,%9}, {%0,%1,%2,%3};"
                 : "+f"(d[0]), "+f"(d[1]), "+f"(d[2]), "+f"(d[3])
                 : "r"(a0), "r"(a1), "r"(a2), "r"(a3), "r"(b0), "r"(b1));
}
__device__ __forceinline__ void mma_f16(float d[4], const uint32_t a0, const uint32_t a1,
                                        const uint32_t a2, const uint32_t a3,
                                        const uint32_t b0, const uint32_t b1) {
    asm volatile("mma.sync.aligned.m16n8k16.row.col.f32.f16.f16.f32 "
                 "{%0,%1,%2,%3}, {%4,%5,%6,%7}, {%8,%9}, {%0,%1,%2,%3};"
                 : "+f"(d[0]), "+f"(d[1]), "+f"(d[2]), "+f"(d[3])
                 : "r"(a0), "r"(a1), "r"(a2), "r"(a3), "r"(b0), "r"(b1));
}
__device__ __forceinline__ void cp16(uint32_t saddr, const void* gaddr) {
    asm volatile("cp.async.cg.shared.global [%0], [%1], 16;" :: "r"(saddr), "l"(gaddr));
}
#define CP_COMMIT() asm volatile("cp.async.commit_group;" ::: "memory")
#define CP_WAIT1()  asm volatile("cp.async.wait_group 1;" ::: "memory")

// ---------------- GroupNorm partial stats ----------------
__global__ void gn_partial(const float* __restrict__ x) {
    int bg = blockIdx.x;
    int chunk = blockIdx.y;
    const float4* p = (const float4*)(x + (size_t)bg * 32 * 4096 + (size_t)chunk * 8192);
    float s = 0.f, q = 0.f;
#pragma unroll
    for (int i = 0; i < 8; i++) {
        float4 v = p[threadIdx.x + i * 256];
        s += v.x + v.y + v.z + v.w;
        q += v.x * v.x + v.y * v.y + v.z * v.z + v.w * v.w;
    }
    __shared__ float ss[256], sq[256];
    ss[threadIdx.x] = s; sq[threadIdx.x] = q;
    __syncthreads();
    for (int o = 128; o > 0; o >>= 1) {
        if (threadIdx.x < o) {
            ss[threadIdx.x] += ss[threadIdx.x + o];
            sq[threadIdx.x] += sq[threadIdx.x + o];
        }
        __syncthreads();
    }
    if (threadIdx.x == 0) {
        g_part[(bg * 16 + chunk) * 2 + 0] = ss[0];
        g_part[(bg * 16 + chunk) * 2 + 1] = sq[0];
    }
}

// ---------------- Weight pre-fragmentation (bf16 A-frag order) ----------------
__global__ void w_frag(const float* __restrict__ Wq, const float* __restrict__ Wp) {
    int e = blockIdx.x * 256 + threadIdx.x;   // 0..32767
    const float* W;
    uint4* dst;
    int idx;
    if (e < 24576) { W = Wq; dst = g_wqf; idx = e; }
    else           { W = Wp; dst = g_wpf; idx = e - 24576; }
    int lane = idx & 31, wid = (idx >> 5) & 7, ks = (idx >> 8) & 15, mb = idx >> 12;
    int gr = lane >> 2, tg = lane & 3;
    const float* ap = W + (size_t)(mb * 128 + wid * 16 + gr) * 256 + ks * 16 + 2 * tg;
    float2 w00 = *(const float2*)ap;
    float2 w10 = *(const float2*)(ap + 8 * 256);
    float2 w01 = *(const float2*)(ap + 8);
    float2 w11 = *(const float2*)(ap + 8 * 256 + 8);
    uint4 u;
    u.x = pbf2(w00.x, w00.y);
    u.y = pbf2(w10.x, w10.y);
    u.z = pbf2(w01.x, w01.y);
    u.w = pbf2(w11.x, w11.y);
    dst[idx] = u;
}

// ---------------- QKV GEMM: cp.async A-frags, GN-fused inline B ----------------
// smem: Af 2 stages x 4KB @0 | Bf 4KB @8192 | Ost overlay @0 | sc @33280 | sh @34304
#define QKV_SMEM 35328

__global__ void __launch_bounds__(256) gemm_qkv(const float* __restrict__ x,
                                                const float* __restrict__ bias,
                                                const float* __restrict__ nw,
                                                const float* __restrict__ nbv) {
    extern __shared__ char sm[];
    uint32_t sb;
    asm("{ .reg .u64 t; cvta.to.shared.u64 t, %1; cvt.u32.u64 %0, t; }" : "=r"(sb) : "l"(sm));
    uint2* Bf = (uint2*)(sm + 8192);
    unsigned short* Ost = (unsigned short*)sm;      // [128][130] 16-bit overlay
    float* sc = (float*)(sm + 33280);
    float* sh = (float*)(sm + 34304);

    const int tid = threadIdx.x, wid = tid >> 5, lane = tid & 31;
    const int gr = lane >> 2, tg = lane & 3;
    const int n0 = blockIdx.x * 128, mb = blockIdx.y, b = blockIdx.z;
    const int wm = wid & 3, wn = wid >> 2;

    {
        int c = tid;
        int bg = b * 8 + (c >> 5);
        float s_ = 0.f, q_ = 0.f;
#pragma unroll
        for (int i = 0; i < 16; i++) {
            s_ += g_part[(bg * 16 + i) * 2 + 0];
            q_ += g_part[(bg * 16 + i) * 2 + 1];
        }
        const float inv = 1.0f / 131072.0f;
        float mean = s_ * inv;
        float var = q_ * inv - mean * mean;
        float rstd = rsqrtf(var + EPSV);
        float s = rstd * nw[c];
        sc[c] = s;
        sh[c] = nbv[c] - mean * s;
    }

    float acc[2][8][4] = {};

    // prefetch A frags for ks=0
    cp16(sb + tid * 16, g_wqf + (size_t)(mb * 16) * 256 + tid);
    CP_COMMIT();
    __syncthreads();   // sc/sh ready

    for (int ks = 0; ks < 16; ks++) {
        // B frags inline (GN fused); x is L2-resident
#pragma unroll
        for (int i = 0; i < 2; i++) {
            int u_ = wid * 2 + i;
            int n = n0 + u_ * 8 + gr;
            int c0 = ks * 16 + 2 * tg;
            const float* xp = x + ((size_t)(b * 256 + c0)) * 4096 + n;
            float h00 = xp[0] * sc[c0] + sh[c0];
            float h01 = xp[4096] * sc[c0 + 1] + sh[c0 + 1];
            float h10 = xp[8 * 4096] * sc[c0 + 8] + sh[c0 + 8];
            float h11 = xp[9 * 4096] * sc[c0 + 9] + sh[c0 + 9];
            uint2 v;
            v.x = pbf2(h00, h01);
            v.y = pbf2(h10, h11);
            Bf[u_ * 32 + lane] = v;
        }
        if (ks + 1 < 16)
            cp16(sb + ((ks + 1) & 1) * 4096 + tid * 16,
                 g_wqf + (size_t)(mb * 16 + ks + 1) * 256 + tid);
        CP_COMMIT();
        CP_WAIT1();
        __syncthreads();

        const uint4* AfS = (const uint4*)(sm + (ks & 1) * 4096);
        uint4 a0 = AfS[(wm * 2 + 0) * 32 + lane];
        uint4 a1 = AfS[(wm * 2 + 1) * 32 + lane];
#pragma unroll
        for (int u_ = 0; u_ < 8; u_++) {
            uint2 bb = Bf[(wn * 8 + u_) * 32 + lane];
            mma_bf16(acc[0][u_], a0.x, a0.y, a0.z, a0.w, bb.x, bb.y);
            mma_bf16(acc[1][u_], a1.x, a1.y, a1.z, a1.w, bb.x, bb.y);
        }
        __syncthreads();
    }

    const float scale = (mb < 2) ? 0.125f * 1.4426950408889634f : 1.0f;
    const bool v_half = (mb >= 4);
#pragma unroll
    for (int t = 0; t < 2; t++) {
        int o_l = wm * 32 + t * 16 + gr;
        float bi0 = bias[mb * 128 + o_l];
        float bi1 = bias[mb * 128 + o_l + 8];
#pragma unroll
        for (int u_ = 0; u_ < 8; u_++) {
            int n_l = wn * 64 + u_ * 8 + 2 * tg;
            float v00 = (acc[t][u_][0] + bi0) * scale, v01 = (acc[t][u_][1] + bi0) * scale;
            float v10 = (acc[t][u_][2] + bi1) * scale, v11 = (acc[t][u_][3] + bi1) * scale;
            uint32_t w0 = v_half ? ph2(v00, v01) : pbf2(v00, v01);
            uint32_t w1 = v_half ? ph2(v10, v11) : pbf2(v10, v11);
            *(uint32_t*)&Ost[o_l * 130 + n_l] = w0;
            *(uint32_t*)&Ost[(o_l + 8) * 130 + n_l] = w1;
        }
    }
    __syncthreads();

    if (mb < 2) {
#pragma unroll
        for (int p = 0; p < 32; p++) {
            int idx = tid + p * 256;
            int n = idx >> 6;
            int ho = (idx >> 5) & 1;
            int cw = idx & 31;
            unsigned short lo = Ost[(ho * 64 + 2 * cw) * 130 + n];
            unsigned short hi = Ost[(ho * 64 + 2 * cw + 1) * 130 + n];
            uint32_t val = (uint32_t)lo | ((uint32_t)hi << 16);
            int bh = b * 4 + mb * 2 + ho;
            ((uint32_t*)g_qb)[((size_t)bh * 4096 + n0 + n) * 32 + cw] = val;
        }
    } else if (mb < 4) {
#pragma unroll
        for (int p = 0; p < 8; p++) {
            int e = tid + p * 256;
            int ln = e & 31, sp = (e >> 5) & 1, kt = (e >> 6) & 15, ho = e >> 10;
            int egr = ln >> 2, etg = ln & 3;
            int n = kt * 8 + egr;
            uint4 r;
            {
                int c0 = ho * 64 + (2 * sp) * 16 + 2 * etg;
                r.x = (uint32_t)Ost[c0 * 130 + n] | ((uint32_t)Ost[(c0 + 1) * 130 + n] << 16);
                r.y = (uint32_t)Ost[(c0 + 8) * 130 + n] | ((uint32_t)Ost[(c0 + 9) * 130 + n] << 16);
            }
            {
                int c0 = ho * 64 + (2 * sp + 1) * 16 + 2 * etg;
                r.z = (uint32_t)Ost[c0 * 130 + n] | ((uint32_t)Ost[(c0 + 1) * 130 + n] << 16);
                r.w = (uint32_t)Ost[(c0 + 8) * 130 + n] | ((uint32_t)Ost[(c0 + 9) * 130 + n] << 16);
            }
            int bh = b * 4 + (mb & 1) * 2 + ho;
            g_kf4[(((size_t)bh * 512 + (n0 >> 3) + kt) * 2 + sp) * 32 + ln] = r;
        }
    } else {
        int chv = blockIdx.x;
#pragma unroll
        for (int p = 0; p < 8; p++) {
            int e = tid + p * 256;
            int ln = e & 31, sp = (e >> 5) & 3, ct = (e >> 7) & 7, ho = e >> 10;
            int egr = ln >> 2, etg = ln & 3;
            int c = ho * 64 + ct * 8 + egr;
            uint4 r;
            {
                int nn = (2 * sp) * 16 + 2 * etg;
                r.x = *(uint32_t*)&Ost[c * 130 + nn];
                r.y = *(uint32_t*)&Ost[c * 130 + nn + 8];
            }
            {
                int nn = (2 * sp + 1) * 16 + 2 * etg;
                r.z = *(uint32_t*)&Ost[c * 130 + nn];
                r.w = *(uint32_t*)&Ost[c * 130 + nn + 8];
            }
            int bh = b * 4 + (mb - 4) * 2 + ho;
            g_vf4[((((size_t)bh * 32 + chv) * 8 + ct) * 4 + sp) * 32 + ln] = r;
        }
    }
}

// ---------------- Proj GEMM: fully cp.async 3-stage ring (both operands) ---------
// smem: 3 stages x (A 4KB | B 4KB) = 24KB
#define PROJ_SMEM 24576

__global__ void __launch_bounds__(256) gemm_proj(const float* __restrict__ bias,
                                                 const float* __restrict__ resid,
                                                 float* __restrict__ outp) {
    extern __shared__ char smp[];
    uint32_t sb;
    asm("{ .reg .u64 t; cvta.to.shared.u64 t, %1; cvt.u32.u64 %0, t; }" : "=r"(sb) : "l"(smp));
    const int tid = threadIdx.x, wid = tid >> 5, lane = tid & 31;
    const int gr = lane >> 2, tg = lane & 3;
    const int n0 = blockIdx.x * 128, mb = blockIdx.y, b = blockIdx.z;
    const int wm = wid & 3, wn = wid >> 2;

    float acc[2][8][4] = {};

#define PPREF(ks) do {                                                        \
        int _k = (ks);                                                       \
        if (_k < 16) {                                                       \
            uint32_t _st = sb + (uint32_t)(_k % 3) * 8192;                   \
            const uint4* _ga = g_wpf + (size_t)(mb * 16 + _k) * 256;         \
            const uint4* _gb = (const uint4*)(g_aof +                        \
                (((size_t)(b * 16 + _k) * 512 + (n0 >> 3)) * 32));           \
            cp16(_st + tid * 16, _ga + tid);                                 \
            cp16(_st + 4096 + tid * 16, _gb + tid);                          \
        }                                                                    \
        CP_COMMIT();                                                         \
    } while (0)

    PPREF(0);
    PPREF(1);

    for (int ks = 0; ks < 16; ks++) {
        CP_WAIT1();
        __syncthreads();
        PPREF(ks + 2);

        const uint4* AfS = (const uint4*)(smp + (ks % 3) * 8192);
        const uint2* BfS = (const uint2*)(smp + (ks % 3) * 8192 + 4096);
        uint4 a0 = AfS[(wm * 2 + 0) * 32 + lane];
        uint4 a1 = AfS[(wm * 2 + 1) * 32 + lane];
#pragma unroll
        for (int u_ = 0; u_ < 8; u_++) {
            uint2 bb = BfS[(wn * 8 + u_) * 32 + lane];
            mma_bf16(acc[0][u_], a0.x, a0.y, a0.z, a0.w, bb.x, bb.y);
            mma_bf16(acc[1][u_], a1.x, a1.y, a1.z, a1.w, bb.x, bb.y);
        }
    }
#undef PPREF

#pragma unroll
    for (int t = 0; t < 2; t++) {
        int o = mb * 128 + wm * 32 + t * 16 + gr;
        float bi0 = bias[o], bi1 = bias[o + 8];
#pragma unroll
        for (int u_ = 0; u_ < 8; u_++) {
            size_t off = ((size_t)(b * 256 + o)) * 4096 + n0 + wn * 64 + u_ * 8 + 2 * tg;
            float2 r0 = *(const float2*)(resid + off);
            float2 o0;
            o0.x = acc[t][u_][0] + bi0 + r0.x;
            o0.y = acc[t][u_][1] + bi0 + r0.y;
            *(float2*)(outp + off) = o0;
            size_t off8 = off + 8 * 4096;
            float2 r1 = *(const float2*)(resid + off8);
            float2 o1;
            o1.x = acc[t][u_][2] + bi1 + r1.x;
            o1.y = acc[t][u_][3] + bi1 + r1.y;
            *(float2*)(outp + off8) = o1;
        }
    }
}

// ---------------- flash attention (R14 version, verbatim) ----------------
#define ATT_SMEM 98304
#define ONE2 0x3C003C00u

__global__ void __launch_bounds__(128, 2) attn_mma() {
    extern __shared__ char smc[];
    uint32_t sbase;
    asm("{ .reg .u64 t; cvta.to.shared.u64 t, %1; cvt.u32.u64 %0, t; }" : "=r"(sbase) : "l"(smc));

    const int tid = threadIdx.x, wid = tid >> 5, lane = tid & 31;
    const int gr = lane >> 2, tg = lane & 3;
    const int qt = blockIdx.x, bh = blockIdx.y;
    const int b = bh >> 2, hh = bh & 3;
    const int w32 = wid * 32;

    const __nv_bfloat16* qg = g_qb + ((size_t)bh * 4096 + qt * 128) * 64;
    const uint4* kfg = g_kf4 + (size_t)bh * 32768;
    const uint4* vfg = g_vf4 + (size_t)bh * 32768;

    uint32_t qa[2][4][4];
#pragma unroll
    for (int at = 0; at < 2; at++) {
#pragma unroll
        for (int s = 0; s < 4; s++) {
            const __nv_bfloat16* base = qg + (size_t)(w32 + at * 16 + gr) * 64 + s * 16 + 2 * tg;
            qa[at][s][0] = *(const uint32_t*)(base);
            qa[at][s][1] = *(const uint32_t*)(base + 8 * 64);
            qa[at][s][2] = *(const uint32_t*)(base + 8);
            qa[at][s][3] = *(const uint32_t*)(base + 8 * 64 + 8);
        }
    }

    float oacc[2][8][4] = {};
    float rsacc[2][4] = {};

#define PREFETCH(ch) do {                                                     \
        int _c = (ch);                                                       \
        if (_c < 32) {                                                       \
            uint32_t _sk = sbase + (uint32_t)(_c % 3) * 32768;               \
            const uint4* _gk = kfg + (size_t)_c * 1024;                      \
            const uint4* _gv = vfg + (size_t)_c * 1024;                      \
            _Pragma("unroll")                                                \
            for (int _i = 0; _i < 8; _i++)                                   \
                cp16(_sk + (tid + _i * 128) * 16, _gk + tid + _i * 128);     \
            _Pragma("unroll")                                                \
            for (int _i = 0; _i < 8; _i++)                                   \
                cp16(_sk + 16384 + (tid + _i * 128) * 16, _gv + tid + _i * 128); \
        }                                                                    \
        CP_COMMIT();                                                         \
    } while (0)

#define S_CALC(dst, g) do {                                                  \
        _Pragma("unroll")                                                    \
        for (int _u = 0; _u < 4; _u++) {                                     \
            uint4 _k0 = Kf4[(((g) * 4 + _u) * 2 + 0) * 32 + lane];           \
            uint4 _k1 = Kf4[(((g) * 4 + _u) * 2 + 1) * 32 + lane];           \
            _Pragma("unroll")                                                \
            for (int _at = 0; _at < 2; _at++) {                              \
                dst[_at][_u][0] = 0.f; dst[_at][_u][1] = 0.f;                \
                dst[_at][_u][2] = 0.f; dst[_at][_u][3] = 0.f;                \
                mma_bf16(dst[_at][_u], qa[_at][0][0], qa[_at][0][1], qa[_at][0][2], qa[_at][0][3], _k0.x, _k0.y); \
                mma_bf16(dst[_at][_u], qa[_at][1][0], qa[_at][1][1], qa[_at][1][2], qa[_at][1][3], _k0.z, _k0.w); \
                mma_bf16(dst[_at][_u], qa[_at][2][0], qa[_at][2][1], qa[_at][2][2], qa[_at][2][3], _k1.x, _k1.y); \
                mma_bf16(dst[_at][_u], qa[_at][3][0], qa[_at][3][1], qa[_at][3][2], qa[_at][3][3], _k1.z, _k1.w); \
            }                                                                \
        }                                                                    \
    } while (0)

#define E_CALC(pdst, src) do {                                               \
        _Pragma("unroll")                                                    \
        for (int _at = 0; _at < 2; _at++) {                                  \
            _Pragma("unroll")                                                \
            for (int _u = 0; _u < 4; _u++) {                                 \
                pdst[_at][_u][0] = ex2h2(ph2(src[_at][_u][0], src[_at][_u][1])); \
                pdst[_at][_u][1] = ex2h2(ph2(src[_at][_u][2], src[_at][_u][3])); \
            }                                                                \
        }                                                                    \
    } while (0)

#define V_CALC(g, psrc) do {                                                 \
        _Pragma("unroll")                                                    \
        for (int _ct = 0; _ct < 8; _ct++) {                                  \
            uint4 _v = Vf4[(_ct * 4 + (g)) * 32 + lane];                     \
            _Pragma("unroll")                                                \
            for (int _at = 0; _at < 2; _at++) {                              \
                mma_f16(oacc[_at][_ct], psrc[_at][0][0], psrc[_at][0][1],    \
                        psrc[_at][1][0], psrc[_at][1][1], _v.x, _v.y);       \
                mma_f16(oacc[_at][_ct], psrc[_at][2][0], psrc[_at][2][1],    \
                        psrc[_at][3][0], psrc[_at][3][1], _v.z, _v.w);       \
            }                                                                \
        }                                                                    \
        _Pragma("unroll")                                                    \
        for (int _at = 0; _at < 2; _at++) {                                  \
            mma_f16(rsacc[_at], psrc[_at][0][0], psrc[_at][0][1],            \
                    psrc[_at][1][0], psrc[_at][1][1], ONE2, ONE2);           \
            mma_f16(rsacc[_at], psrc[_at][2][0], psrc[_at][2][1],            \
                    psrc[_at][3][0], psrc[_at][3][1], ONE2, ONE2);           \
        }                                                                    \
    } while (0)

    PREFETCH(0);
    PREFETCH(1);

    for (int ch = 0; ch < 32; ch++) {
        CP_WAIT1();
        __syncthreads();
        PREFETCH(ch + 2);

        const uint4* Kf4 = (const uint4*)(smc + (ch % 3) * 32768);
        const uint4* Vf4 = (const uint4*)(smc + (ch % 3) * 32768 + 16384);

        float sA[2][4][4], sB[2][4][4];
        uint32_t pA[2][4][2], pB[2][4][2];

        S_CALC(sA, 0);
        E_CALC(pA, sA);
        S_CALC(sB, 1);
        V_CALC(0, pA);
        E_CALC(pB, sB);
        S_CALC(sA, 2);
        V_CALC(1, pB);
        E_CALC(pA, sA);
        S_CALC(sB, 3);
        V_CALC(2, pA);
        E_CALC(pB, sB);
        V_CALC(3, pB);
    }
#undef PREFETCH
#undef S_CALC
#undef E_CALC
#undef V_CALC

    float ri[2][2];
#pragma unroll
    for (int at = 0; at < 2; at++) {
        ri[at][0] = 1.0f / rsacc[at][0];
        ri[at][1] = 1.0f / rsacc[at][2];
    }

    // write O directly in proj's B-fragment order (coalesced uint2)
#pragma unroll
    for (int at = 0; at < 2; at++) {
        int nt0 = qt * 16 + wid * 4 + at * 2;
#pragma unroll
        for (int kgl = 0; kgl < 4; kgl++) {
            int kg = hh * 4 + kgl;
            uint2 f0, f1;
            f0.x = pbf2(oacc[at][2 * kgl][0] * ri[at][0], oacc[at][2 * kgl][1] * ri[at][0]);
            f0.y = pbf2(oacc[at][2 * kgl + 1][0] * ri[at][0], oacc[at][2 * kgl + 1][1] * ri[at][0]);
            f1.x = pbf2(oacc[at][2 * kgl][2] * ri[at][1], oacc[at][2 * kgl][3] * ri[at][1]);
            f1.y = pbf2(oacc[at][2 * kgl + 1][2] * ri[at][1], oacc[at][2 * kgl + 1][3] * ri[at][1]);
            size_t base = ((size_t)(b * 16 + kg) * 512 + nt0) * 32 + lane;
            g_aof[base] = f0;
            g_aof[base + 32] = f1;
        }
    }
}

// ---------------- launch ----------------
extern "C" void kernel_launch(void* const* d_in, const int* in_sizes, int n_in,
                              void* d_out, int out_size) {
    (void)in_sizes; (void)n_in; (void)out_size;
    const float* x      = (const float*)d_in[0];
    const float* norm_w = (const float*)d_in[1];
    const float* norm_b = (const float*)d_in[2];
    const float* qkv_w  = (const float*)d_in[3];
    const float* qkv_b  = (const float*)d_in[4];
    const float* proj_w = (const float*)d_in[5];
    const float* proj_b = (const float*)d_in[6];
    float* out = (float*)d_out;

    cudaFuncSetAttribute(attn_mma, cudaFuncAttributeMaxDynamicSharedMemorySize, ATT_SMEM);

    gn_partial<<<dim3(32, 16), 256>>>(x);
    w_frag<<<128, 256>>>(qkv_w, proj_w);

    gemm_qkv<<<dim3(32, 6, 4), 256, QKV_SMEM>>>(x, qkv_b, norm_w, norm_b);

    attn_mma<<<dim3(32, 16), 128, ATT_SMEM>>>();

    gemm_proj<<<dim3(32, 2, 4), 256, PROJ_SMEM>>>(proj_b, x, out);
}

// round 16
// speedup vs baseline: 1.2084x; 1.0318x over previous
#include <cuda_runtime.h>
#include <cuda_bf16.h>
#include <cuda_fp16.h>
#include <math.h>
#include <cstdint>

#define EPSV 1e-5f

// ---------------- scratch (device globals; allocation-free) ----------------
__device__ __nv_bfloat16 g_qb[16 * 4096 * 64];   // q: [bh][n][c], pre-scaled 0.125*log2e
__device__ uint4 g_kf4[16 * 512 * 2 * 32];       // K frags (bf16): [bh][kt][sp][lane]
__device__ uint4 g_vf4[16 * 32 * 8 * 4 * 32];    // V frags (fp16): [bh][chunk][ct][sp][lane]
__device__ uint2 g_aof[4 * 16 * 512 * 32];       // attention out, proj-B-frag order
__device__ uint4 g_wqf[6 * 16 * 8 * 32];         // qkv W, A-frag order [mb][ks][wid][lane]
__device__ uint4 g_wpf[2 * 16 * 8 * 32];         // proj W, A-frag order
__device__ float g_part[32 * 16 * 2];

// ======================= helpers =======================
__device__ __forceinline__ uint32_t pbf2(float lo, float hi) {
    __nv_bfloat162 t = __floats2bfloat162_rn(lo, hi);
    return *(uint32_t*)&t;
}
__device__ __forceinline__ uint32_t ph2(float lo, float hi) {
    __half2 t = __floats2half2_rn(lo, hi);
    return *(uint32_t*)&t;
}
__device__ __forceinline__ uint32_t ex2h2(uint32_t h2) {
    uint32_t r;
    asm("ex2.approx.f16x2 %0, %1;" : "=r"(r) : "r"(h2));
    return r;
}
__device__ __forceinline__ void mma_bf16(float d[4], const uint32_t a0, const uint32_t a1,
                                         const uint32_t a2, const uint32_t a3,
                                         const uint32_t b0, const uint32_t b1) {
    asm volatile("mma.sync.aligned.m16n8k16.row.col.f32.bf16.bf16.f32 "
                 "{%0,%1,%2,%3}, {%4,%5,%6,%7}, {%8,%9}, {%0,%1,%2,%3};"
                 : "+f"(d[0]), "+f"(d[1]), "+f"(d[2]), "+f"(d[3])
                 : "r"(a0), "r"(a1), "r"(a2), "r"(a3), "r"(b0), "r"(b1));
}
__device__ __forceinline__ void mma_f16(float d[4], const uint32_t a0, const uint32_t a1,
                                        const uint32_t a2, const uint32_t a3,
                                        const uint32_t b0, const uint32_t b1) {
    asm volatile("mma.sync.aligned.m16n8k16.row.col.f32.f16.f16.f32 "
                 "{%0,%1,%2,%3}, {%4,%5,%6,%7}, {%8,%9}, {%0,%1,%2,%3};"
                 : "+f"(d[0]), "+f"(d[1]), "+f"(d[2]), "+f"(d[3])
                 : "r"(a0), "r"(a1), "r"(a2), "r"(a3), "r"(b0), "r"(b1));
}
__device__ __forceinline__ void cp16(uint32_t saddr, const void* gaddr) {
    asm volatile("cp.async.cg.shared.global [%0], [%1], 16;" :: "r"(saddr), "l"(gaddr));
}
#define CP_COMMIT() asm volatile("cp.async.commit_group;" ::: "memory")
#define CP_WAIT1()  asm volatile("cp.async.wait_group 1;" ::: "memory")
#define CP_WAIT0()  asm volatile("cp.async.wait_group 0;" ::: "memory")

// ---------------- GroupNorm partial stats + weight pre-fragmentation (fused) ------
__global__ void gn_wfrag(const float* __restrict__ x,
                         const float* __restrict__ Wq, const float* __restrict__ Wp) {
    if (blockIdx.x < 512) {
        int bg = blockIdx.x >> 4;
        int chunk = blockIdx.x & 15;
        const float4* p = (const float4*)(x + (size_t)bg * 32 * 4096 + (size_t)chunk * 8192);
        float s = 0.f, q = 0.f;
#pragma unroll
        for (int i = 0; i < 8; i++) {
            float4 v = p[threadIdx.x + i * 256];
            s += v.x + v.y + v.z + v.w;
            q += v.x * v.x + v.y * v.y + v.z * v.z + v.w * v.w;
        }
        __shared__ float ss[256], sq[256];
        ss[threadIdx.x] = s; sq[threadIdx.x] = q;
        __syncthreads();
        for (int o = 128; o > 0; o >>= 1) {
            if (threadIdx.x < o) {
                ss[threadIdx.x] += ss[threadIdx.x + o];
                sq[threadIdx.x] += sq[threadIdx.x + o];
            }
            __syncthreads();
        }
        if (threadIdx.x == 0) {
            g_part[(bg * 16 + chunk) * 2 + 0] = ss[0];
            g_part[(bg * 16 + chunk) * 2 + 1] = sq[0];
        }
    } else {
        int e = (blockIdx.x - 512) * 256 + threadIdx.x;   // 0..32767
        const float* W;
        uint4* dst;
        int idx;
        if (e < 24576) { W = Wq; dst = g_wqf; idx = e; }
        else           { W = Wp; dst = g_wpf; idx = e - 24576; }
        int lane = idx & 31, wid = (idx >> 5) & 7, ks = (idx >> 8) & 15, mb = idx >> 12;
        int gr = lane >> 2, tg = lane & 3;
        const float* ap = W + (size_t)(mb * 128 + wid * 16 + gr) * 256 + ks * 16 + 2 * tg;
        float2 w00 = *(const float2*)ap;
        float2 w10 = *(const float2*)(ap + 8 * 256);
        float2 w01 = *(const float2*)(ap + 8);
        float2 w11 = *(const float2*)(ap + 8 * 256 + 8);
        uint4 u;
        u.x = pbf2(w00.x, w00.y);
        u.y = pbf2(w10.x, w10.y);
        u.z = pbf2(w01.x, w01.y);
        u.w = pbf2(w11.x, w11.y);
        dst[idx] = u;
    }
}

// ---------------- QKV GEMM: cp.async A-frags, GN-fused inline B ----------------
#define QKV_SMEM 35328

__global__ void __launch_bounds__(256) gemm_qkv(const float* __restrict__ x,
                                                const float* __restrict__ bias,
                                                const float* __restrict__ nw,
                                                const float* __restrict__ nbv) {
    extern __shared__ char sm[];
    uint32_t sb;
    asm("{ .reg .u64 t; cvta.to.shared.u64 t, %1; cvt.u32.u64 %0, t; }" : "=r"(sb) : "l"(sm));
    uint2* Bf = (uint2*)(sm + 8192);
    unsigned short* Ost = (unsigned short*)sm;      // [128][130] 16-bit overlay
    float* sc = (float*)(sm + 33280);
    float* sh = (float*)(sm + 34304);

    const int tid = threadIdx.x, wid = tid >> 5, lane = tid & 31;
    const int gr = lane >> 2, tg = lane & 3;
    const int n0 = blockIdx.x * 128, mb = blockIdx.y, b = blockIdx.z;
    const int wm = wid & 3, wn = wid >> 2;

    {
        int c = tid;
        int bg = b * 8 + (c >> 5);
        float s_ = 0.f, q_ = 0.f;
#pragma unroll
        for (int i = 0; i < 16; i++) {
            s_ += g_part[(bg * 16 + i) * 2 + 0];
            q_ += g_part[(bg * 16 + i) * 2 + 1];
        }
        const float inv = 1.0f / 131072.0f;
        float mean = s_ * inv;
        float var = q_ * inv - mean * mean;
        float rstd = rsqrtf(var + EPSV);
        float s = rstd * nw[c];
        sc[c] = s;
        sh[c] = nbv[c] - mean * s;
    }

    float acc[2][8][4] = {};

    cp16(sb + tid * 16, g_wqf + (size_t)(mb * 16) * 256 + tid);
    CP_COMMIT();
    __syncthreads();

    for (int ks = 0; ks < 16; ks++) {
#pragma unroll
        for (int i = 0; i < 2; i++) {
            int u_ = wid * 2 + i;
            int n = n0 + u_ * 8 + gr;
            int c0 = ks * 16 + 2 * tg;
            const float* xp = x + ((size_t)(b * 256 + c0)) * 4096 + n;
            float h00 = xp[0] * sc[c0] + sh[c0];
            float h01 = xp[4096] * sc[c0 + 1] + sh[c0 + 1];
            float h10 = xp[8 * 4096] * sc[c0 + 8] + sh[c0 + 8];
            float h11 = xp[9 * 4096] * sc[c0 + 9] + sh[c0 + 9];
            uint2 v;
            v.x = pbf2(h00, h01);
            v.y = pbf2(h10, h11);
            Bf[u_ * 32 + lane] = v;
        }
        if (ks + 1 < 16)
            cp16(sb + ((ks + 1) & 1) * 4096 + tid * 16,
                 g_wqf + (size_t)(mb * 16 + ks + 1) * 256 + tid);
        CP_COMMIT();
        CP_WAIT1();
        __syncthreads();

        const uint4* AfS = (const uint4*)(sm + (ks & 1) * 4096);
        uint4 a0 = AfS[(wm * 2 + 0) * 32 + lane];
        uint4 a1 = AfS[(wm * 2 + 1) * 32 + lane];
#pragma unroll
        for (int u_ = 0; u_ < 8; u_++) {
            uint2 bb = Bf[(wn * 8 + u_) * 32 + lane];
            mma_bf16(acc[0][u_], a0.x, a0.y, a0.z, a0.w, bb.x, bb.y);
            mma_bf16(acc[1][u_], a1.x, a1.y, a1.z, a1.w, bb.x, bb.y);
        }
        __syncthreads();
    }

    const float scale = (mb < 2) ? 0.125f * 1.4426950408889634f : 1.0f;
    const bool v_half = (mb >= 4);
#pragma unroll
    for (int t = 0; t < 2; t++) {
        int o_l = wm * 32 + t * 16 + gr;
        float bi0 = bias[mb * 128 + o_l];
        float bi1 = bias[mb * 128 + o_l + 8];
#pragma unroll
        for (int u_ = 0; u_ < 8; u_++) {
            int n_l = wn * 64 + u_ * 8 + 2 * tg;
            float v00 = (acc[t][u_][0] + bi0) * scale, v01 = (acc[t][u_][1] + bi0) * scale;
            float v10 = (acc[t][u_][2] + bi1) * scale, v11 = (acc[t][u_][3] + bi1) * scale;
            uint32_t w0 = v_half ? ph2(v00, v01) : pbf2(v00, v01);
            uint32_t w1 = v_half ? ph2(v10, v11) : pbf2(v10, v11);
            *(uint32_t*)&Ost[o_l * 130 + n_l] = w0;
            *(uint32_t*)&Ost[(o_l + 8) * 130 + n_l] = w1;
        }
    }
    __syncthreads();

    if (mb < 2) {
#pragma unroll
        for (int p = 0; p < 32; p++) {
            int idx = tid + p * 256;
            int n = idx >> 6;
            int ho = (idx >> 5) & 1;
            int cw = idx & 31;
            unsigned short lo = Ost[(ho * 64 + 2 * cw) * 130 + n];
            unsigned short hi = Ost[(ho * 64 + 2 * cw + 1) * 130 + n];
            uint32_t val = (uint32_t)lo | ((uint32_t)hi << 16);
            int bh = b * 4 + mb * 2 + ho;
            ((uint32_t*)g_qb)[((size_t)bh * 4096 + n0 + n) * 32 + cw] = val;
        }
    } else if (mb < 4) {
#pragma unroll
        for (int p = 0; p < 8; p++) {
            int e = tid + p * 256;
            int ln = e & 31, sp = (e >> 5) & 1, kt = (e >> 6) & 15, ho = e >> 10;
            int egr = ln >> 2, etg = ln & 3;
            int n = kt * 8 + egr;
            uint4 r;
            {
                int c0 = ho * 64 + (2 * sp) * 16 + 2 * etg;
                r.x = (uint32_t)Ost[c0 * 130 + n] | ((uint32_t)Ost[(c0 + 1) * 130 + n] << 16);
                r.y = (uint32_t)Ost[(c0 + 8) * 130 + n] | ((uint32_t)Ost[(c0 + 9) * 130 + n] << 16);
            }
            {
                int c0 = ho * 64 + (2 * sp + 1) * 16 + 2 * etg;
                r.z = (uint32_t)Ost[c0 * 130 + n] | ((uint32_t)Ost[(c0 + 1) * 130 + n] << 16);
                r.w = (uint32_t)Ost[(c0 + 8) * 130 + n] | ((uint32_t)Ost[(c0 + 9) * 130 + n] << 16);
            }
            int bh = b * 4 + (mb & 1) * 2 + ho;
            g_kf4[(((size_t)bh * 512 + (n0 >> 3) + kt) * 2 + sp) * 32 + ln] = r;
        }
    } else {
        int chv = blockIdx.x;
#pragma unroll
        for (int p = 0; p < 8; p++) {
            int e = tid + p * 256;
            int ln = e & 31, sp = (e >> 5) & 3, ct = (e >> 7) & 7, ho = e >> 10;
            int egr = ln >> 2, etg = ln & 3;
            int c = ho * 64 + ct * 8 + egr;
            uint4 r;
            {
                int nn = (2 * sp) * 16 + 2 * etg;
                r.x = *(uint32_t*)&Ost[c * 130 + nn];
                r.y = *(uint32_t*)&Ost[c * 130 + nn + 8];
            }
            {
                int nn = (2 * sp + 1) * 16 + 2 * etg;
                r.z = *(uint32_t*)&Ost[c * 130 + nn];
                r.w = *(uint32_t*)&Ost[c * 130 + nn + 8];
            }
            int bh = b * 4 + (mb - 4) * 2 + ho;
            g_vf4[((((size_t)bh * 32 + chv) * 8 + ct) * 4 + sp) * 32 + ln] = r;
        }
    }
}

// ---------------- Proj GEMM: fully cp.async 3-stage ring (both operands) ---------
#define PROJ_SMEM 24576

__global__ void __launch_bounds__(256) gemm_proj(const float* __restrict__ bias,
                                                 const float* __restrict__ resid,
                                                 float* __restrict__ outp) {
    extern __shared__ char smp[];
    uint32_t sb;
    asm("{ .reg .u64 t; cvta.to.shared.u64 t, %1; cvt.u32.u64 %0, t; }" : "=r"(sb) : "l"(smp));
    const int tid = threadIdx.x, wid = tid >> 5, lane = tid & 31;
    const int gr = lane >> 2, tg = lane & 3;
    const int n0 = blockIdx.x * 128, mb = blockIdx.y, b = blockIdx.z;
    const int wm = wid & 3, wn = wid >> 2;

    float acc[2][8][4] = {};

#define PPREF(ks) do {                                                        \
        int _k = (ks);                                                       \
        if (_k < 16) {                                                       \
            uint32_t _st = sb + (uint32_t)(_k % 3) * 8192;                   \
            const uint4* _ga = g_wpf + (size_t)(mb * 16 + _k) * 256;         \
            const uint4* _gb = (const uint4*)(g_aof +                        \
                (((size_t)(b * 16 + _k) * 512 + (n0 >> 3)) * 32));           \
            cp16(_st + tid * 16, _ga + tid);                                 \
            cp16(_st + 4096 + tid * 16, _gb + tid);                          \
        }                                                                    \
        CP_COMMIT();                                                         \
    } while (0)

    PPREF(0);
    PPREF(1);

    for (int ks = 0; ks < 16; ks++) {
        CP_WAIT1();
        __syncthreads();
        PPREF(ks + 2);

        const uint4* AfS = (const uint4*)(smp + (ks % 3) * 8192);
        const uint2* BfS = (const uint2*)(smp + (ks % 3) * 8192 + 4096);
        uint4 a0 = AfS[(wm * 2 + 0) * 32 + lane];
        uint4 a1 = AfS[(wm * 2 + 1) * 32 + lane];
#pragma unroll
        for (int u_ = 0; u_ < 8; u_++) {
            uint2 bb = BfS[(wn * 8 + u_) * 32 + lane];
            mma_bf16(acc[0][u_], a0.x, a0.y, a0.z, a0.w, bb.x, bb.y);
            mma_bf16(acc[1][u_], a1.x, a1.y, a1.z, a1.w, bb.x, bb.y);
        }
    }
#undef PPREF

#pragma unroll
    for (int t = 0; t < 2; t++) {
        int o = mb * 128 + wm * 32 + t * 16 + gr;
        float bi0 = bias[o], bi1 = bias[o + 8];
#pragma unroll
        for (int u_ = 0; u_ < 8; u_++) {
            size_t off = ((size_t)(b * 256 + o)) * 4096 + n0 + wn * 64 + u_ * 8 + 2 * tg;
            float2 r0 = *(const float2*)(resid + off);
            float2 o0;
            o0.x = acc[t][u_][0] + bi0 + r0.x;
            o0.y = acc[t][u_][1] + bi0 + r0.y;
            *(float2*)(outp + off) = o0;
            size_t off8 = off + 8 * 4096;
            float2 r1 = *(const float2*)(resid + off8);
            float2 o1;
            o1.x = acc[t][u_][2] + bi1 + r1.x;
            o1.y = acc[t][u_][3] + bi1 + r1.y;
            *(float2*)(outp + off8) = o1;
        }
    }
}

// ---------------- flash attention: 2-stage ring, 3 CTAs/SM ----------------
// grid (32 q-tiles, 16 bh), 128 thr = 4 warps x 32 q rows.
// smem: 2 stages x (K 16KB | V 16KB) = 64KB -> 3 CTAs/SM (9 warps/SM).
#define ATT_SMEM 65536
#define ONE2 0x3C003C00u

__global__ void __launch_bounds__(128, 3) attn_mma() {
    extern __shared__ char smc[];
    uint32_t sbase;
    asm("{ .reg .u64 t; cvta.to.shared.u64 t, %1; cvt.u32.u64 %0, t; }" : "=r"(sbase) : "l"(smc));

    const int tid = threadIdx.x, wid = tid >> 5, lane = tid & 31;
    const int gr = lane >> 2, tg = lane & 3;
    const int qt = blockIdx.x, bh = blockIdx.y;
    const int b = bh >> 2, hh = bh & 3;
    const int w32 = wid * 32;

    const __nv_bfloat16* qg = g_qb + ((size_t)bh * 4096 + qt * 128) * 64;
    const uint4* kfg = g_kf4 + (size_t)bh * 32768;
    const uint4* vfg = g_vf4 + (size_t)bh * 32768;

    uint32_t qa[2][4][4];
#pragma unroll
    for (int at = 0; at < 2; at++) {
#pragma unroll
        for (int s = 0; s < 4; s++) {
            const __nv_bfloat16* base = qg + (size_t)(w32 + at * 16 + gr) * 64 + s * 16 + 2 * tg;
            qa[at][s][0] = *(const uint32_t*)(base);
            qa[at][s][1] = *(const uint32_t*)(base + 8 * 64);
            qa[at][s][2] = *(const uint32_t*)(base + 8);
            qa[at][s][3] = *(const uint32_t*)(base + 8 * 64 + 8);
        }
    }

    float oacc[2][8][4] = {};
    float rsacc[2][4] = {};

#define PREFETCH(ch) do {                                                     \
        int _c = (ch);                                                       \
        if (_c < 32) {                                                       \
            uint32_t _sk = sbase + (uint32_t)(_c & 1) * 32768;               \
            const uint4* _gk = kfg + (size_t)_c * 1024;                      \
            const uint4* _gv = vfg + (size_t)_c * 1024;                      \
            _Pragma("unroll")                                                \
            for (int _i = 0; _i < 8; _i++)                                   \
                cp16(_sk + (tid + _i * 128) * 16, _gk + tid + _i * 128);     \
            _Pragma("unroll")                                                \
            for (int _i = 0; _i < 8; _i++)                                   \
                cp16(_sk + 16384 + (tid + _i * 128) * 16, _gv + tid + _i * 128); \
        }                                                                    \
        CP_COMMIT();                                                         \
    } while (0)

#define S_CALC(dst, g) do {                                                  \
        _Pragma("unroll")                                                    \
        for (int _u = 0; _u < 4; _u++) {                                     \
            uint4 _k0 = Kf4[(((g) * 4 + _u) * 2 + 0) * 32 + lane];           \
            uint4 _k1 = Kf4[(((g) * 4 + _u) * 2 + 1) * 32 + lane];           \
            _Pragma("unroll")                                                \
            for (int _at = 0; _at < 2; _at++) {                              \
                dst[_at][_u][0] = 0.f; dst[_at][_u][1] = 0.f;                \
                dst[_at][_u][2] = 0.f; dst[_at][_u][3] = 0.f;                \
                mma_bf16(dst[_at][_u], qa[_at][0][0], qa[_at][0][1], qa[_at][0][2], qa[_at][0][3], _k0.x, _k0.y); \
                mma_bf16(dst[_at][_u], qa[_at][1][0], qa[_at][1][1], qa[_at][1][2], qa[_at][1][3], _k0.z, _k0.w); \
                mma_bf16(dst[_at][_u], qa[_at][2][0], qa[_at][2][1], qa[_at][2][2], qa[_at][2][3], _k1.x, _k1.y); \
                mma_bf16(dst[_at][_u], qa[_at][3][0], qa[_at][3][1], qa[_at][3][2], qa[_at][3][3], _k1.z, _k1.w); \
            }                                                                \
        }                                                                    \
    } while (0)

#define E_CALC(pdst, src) do {                                               \
        _Pragma("unroll")                                                    \
        for (int _at = 0; _at < 2; _at++) {                                  \
            _Pragma("unroll")                                                \
            for (int _u = 0; _u < 4; _u++) {                                 \
                pdst[_at][_u][0] = ex2h2(ph2(src[_at][_u][0], src[_at][_u][1])); \
                pdst[_at][_u][1] = ex2h2(ph2(src[_at][_u][2], src[_at][_u][3])); \
            }                                                                \
        }                                                                    \
    } while (0)

#define V_CALC(g, psrc) do {                                                 \
        _Pragma("unroll")                                                    \
        for (int _ct = 0; _ct < 8; _ct++) {                                  \
            uint4 _v = Vf4[(_ct * 4 + (g)) * 32 + lane];                     \
            _Pragma("unroll")                                                \
            for (int _at = 0; _at < 2; _at++) {                              \
                mma_f16(oacc[_at][_ct], psrc[_at][0][0], psrc[_at][0][1],    \
                        psrc[_at][1][0], psrc[_at][1][1], _v.x, _v.y);       \
                mma_f16(oacc[_at][_ct], psrc[_at][2][0], psrc[_at][2][1],    \
                        psrc[_at][3][0], psrc[_at][3][1], _v.z, _v.w);       \
            }                                                                \
        }                                                                    \
        _Pragma("unroll")                                                    \
        for (int _at = 0; _at < 2; _at++) {                                  \
            mma_f16(rsacc[_at], psrc[_at][0][0], psrc[_at][0][1],            \
                    psrc[_at][1][0], psrc[_at][1][1], ONE2, ONE2);           \
            mma_f16(rsacc[_at], psrc[_at][2][0], psrc[_at][2][1],            \
                    psrc[_at][3][0], psrc[_at][3][1], ONE2, ONE2);           \
        }                                                                    \
    } while (0)

    PREFETCH(0);
    PREFETCH(1);

    for (int ch = 0; ch < 32; ch++) {
        CP_WAIT1();          // stage ch&1 ready
        __syncthreads();

        const uint4* Kf4 = (const uint4*)(smc + (ch & 1) * 32768);
        const uint4* Vf4 = (const uint4*)(smc + (ch & 1) * 32768 + 16384);

        float sA[2][4][4], sB[2][4][4];
        uint32_t pA[2][4][2], pB[2][4][2];

        S_CALC(sA, 0);
        E_CALC(pA, sA);
        S_CALC(sB, 1);
        V_CALC(0, pA);
        E_CALC(pB, sB);
        S_CALC(sA, 2);
        V_CALC(1, pB);
        E_CALC(pA, sA);
        S_CALC(sB, 3);
        V_CALC(2, pA);
        E_CALC(pB, sB);
        V_CALC(3, pB);

        __syncthreads();     // all warps done reading stage ch&1
        PREFETCH(ch + 2);    // refill stage (ch+2)&1 == ch&1
    }
#undef PREFETCH
#undef S_CALC
#undef E_CALC
#undef V_CALC

    float ri[2][2];
#pragma unroll
    for (int at = 0; at < 2; at++) {
        ri[at][0] = 1.0f / rsacc[at][0];
        ri[at][1] = 1.0f / rsacc[at][2];
    }

    // write O directly in proj's B-fragment order (coalesced uint2)
#pragma unroll
    for (int at = 0; at < 2; at++) {
        int nt0 = qt * 16 + wid * 4 + at * 2;
#pragma unroll
        for (int kgl = 0; kgl < 4; kgl++) {
            int kg = hh * 4 + kgl;
            uint2 f0, f1;
            f0.x = pbf2(oacc[at][2 * kgl][0] * ri[at][0], oacc[at][2 * kgl][1] * ri[at][0]);
            f0.y = pbf2(oacc[at][2 * kgl + 1][0] * ri[at][0], oacc[at][2 * kgl + 1][1] * ri[at][0]);
            f1.x = pbf2(oacc[at][2 * kgl][2] * ri[at][1], oacc[at][2 * kgl][3] * ri[at][1]);
            f1.y = pbf2(oacc[at][2 * kgl + 1][2] * ri[at][1], oacc[at][2 * kgl + 1][3] * ri[at][1]);
            size_t base = ((size_t)(b * 16 + kg) * 512 + nt0) * 32 + lane;
            g_aof[base] = f0;
            g_aof[base + 32] = f1;
        }
    }
}

// ---------------- launch ----------------
extern "C" void kernel_launch(void* const* d_in, const int* in_sizes, int n_in,
                              void* d_out, int out_size) {
    (void)in_sizes; (void)n_in; (void)out_size;
    const float* x      = (const float*)d_in[0];
    const float* norm_w = (const float*)d_in[1];
    const float* norm_b = (const float*)d_in[2];
    const float* qkv_w  = (const float*)d_in[3];
    const float* qkv_b  = (const float*)d_in[4];
    const float* proj_w = (const float*)d_in[5];
    const float* proj_b = (const float*)d_in[6];
    float* out = (float*)d_out;

    cudaFuncSetAttribute(attn_mma, cudaFuncAttributeMaxDynamicSharedMemorySize, ATT_SMEM);

    gn_wfrag<<<640, 256>>>(x, qkv_w, proj_w);

    gemm_qkv<<<dim3(32, 6, 4), 256, QKV_SMEM>>>(x, qkv_b, norm_w, norm_b);

    attn_mma<<<dim3(32, 16), 128, ATT_SMEM>>>();

    gemm_proj<<<dim3(32, 2, 4), 256, PROJ_SMEM>>>(proj_b, x, out);
}

// round 17
// speedup vs baseline: 1.2166x; 1.0068x over previous
#include <cuda_runtime.h>
#include <cuda_bf16.h>
#include <cuda_fp16.h>
#include <math.h>
#include <cstdint>

#define EPSV 1e-5f

// ---------------- scratch (device globals; allocation-free) ----------------
__device__ __nv_bfloat16 g_qb[16 * 4096 * 64];   // q: [bh][n][c], pre-scaled 0.125*log2e
__device__ uint4 g_kf4[16 * 512 * 2 * 32];       // K frags (bf16): [bh][kt][sp][lane]
__device__ uint4 g_vf4[16 * 32 * 8 * 4 * 32];    // V frags (fp16): [bh][chunk][ct][sp][lane]
__device__ uint2 g_aof[4 * 16 * 512 * 32];       // attention out, proj-B-frag order
__device__ uint4 g_wqf[6 * 16 * 8 * 32];         // qkv W, A-frag order
__device__ uint4 g_wpf[2 * 16 * 8 * 32];         // proj W, A-frag order
__device__ uint32_t g_po[1024 * 32 * 128];       // partial O (fp16 pairs): [unit][i][tid]
__device__ float g_prs[1024 * 128 * 4];          // partial rowsums: [unit][tid][4]
__device__ float g_part[32 * 16 * 2];

// ======================= helpers =======================
__device__ __forceinline__ uint32_t pbf2(float lo, float hi) {
    __nv_bfloat162 t = __floats2bfloat162_rn(lo, hi);
    return *(uint32_t*)&t;
}
__device__ __forceinline__ uint32_t ph2(float lo, float hi) {
    __half2 t = __floats2half2_rn(lo, hi);
    return *(uint32_t*)&t;
}
__device__ __forceinline__ uint32_t ex2h2(uint32_t h2) {
    uint32_t r;
    asm("ex2.approx.f16x2 %0, %1;" : "=r"(r) : "r"(h2));
    return r;
}
__device__ __forceinline__ void mma_bf16(float d[4], const uint32_t a0, const uint32_t a1,
                                         const uint32_t a2, const uint32_t a3,
                                         const uint32_t b0, const uint32_t b1) {
    asm volatile("mma.sync.aligned.m16n8k16.row.col.f32.bf16.bf16.f32 "
                 "{%0,%1,%2,%3}, {%4,%5,%6,%7}, {%8,%9}, {%0,%1,%2,%3};"
                 : "+f"(d[0]), "+f"(d[1]), "+f"(d[2]), "+f"(d[3])
                 : "r"(a0), "r"(a1), "r"(a2), "r"(a3), "r"(b0), "r"(b1));
}
__device__ __forceinline__ void mma_f16(float d[4], const uint32_t a0, const uint32_t a1,
                                        const uint32_t a2, const uint32_t a3,
                                        const uint32_t b0, const uint32_t b1) {
    asm volatile("mma.sync.aligned.m16n8k16.row.col.f32.f16.f16.f32 "
                 "{%0,%1,%2,%3}, {%4,%5,%6,%7}, {%8,%9}, {%0,%1,%2,%3};"
                 : "+f"(d[0]), "+f"(d[1]), "+f"(d[2]), "+f"(d[3])
                 : "r"(a0), "r"(a1), "r"(a2), "r"(a3), "r"(b0), "r"(b1));
}
__device__ __forceinline__ void cp16(uint32_t saddr, const void* gaddr) {
    asm volatile("cp.async.cg.shared.global [%0], [%1], 16;" :: "r"(saddr), "l"(gaddr));
}
#define CP_COMMIT() asm volatile("cp.async.commit_group;" ::: "memory")
#define CP_WAIT1()  asm volatile("cp.async.wait_group 1;" ::: "memory")

// ---------------- GroupNorm partial stats + weight pre-fragmentation (fused) ------
__global__ void gn_wfrag(const float* __restrict__ x,
                         const float* __restrict__ Wq, const float* __restrict__ Wp) {
    if (blockIdx.x < 512) {
        int bg = blockIdx.x >> 4;
        int chunk = blockIdx.x & 15;
        const float4* p = (const float4*)(x + (size_t)bg * 32 * 4096 + (size_t)chunk * 8192);
        float s = 0.f, q = 0.f;
#pragma unroll
        for (int i = 0; i < 8; i++) {
            float4 v = p[threadIdx.x + i * 256];
            s += v.x + v.y + v.z + v.w;
            q += v.x * v.x + v.y * v.y + v.z * v.z + v.w * v.w;
        }
        __shared__ float ss[256], sq[256];
        ss[threadIdx.x] = s; sq[threadIdx.x] = q;
        __syncthreads();
        for (int o = 128; o > 0; o >>= 1) {
            if (threadIdx.x < o) {
                ss[threadIdx.x] += ss[threadIdx.x + o];
                sq[threadIdx.x] += sq[threadIdx.x + o];
            }
            __syncthreads();
        }
        if (threadIdx.x == 0) {
            g_part[(bg * 16 + chunk) * 2 + 0] = ss[0];
            g_part[(bg * 16 + chunk) * 2 + 1] = sq[0];
        }
    } else {
        int e = (blockIdx.x - 512) * 256 + threadIdx.x;
        const float* W;
        uint4* dst;
        int idx;
        if (e < 24576) { W = Wq; dst = g_wqf; idx = e; }
        else           { W = Wp; dst = g_wpf; idx = e - 24576; }
        int lane = idx & 31, wid = (idx >> 5) & 7, ks = (idx >> 8) & 15, mb = idx >> 12;
        int gr = lane >> 2, tg = lane & 3;
        const float* ap = W + (size_t)(mb * 128 + wid * 16 + gr) * 256 + ks * 16 + 2 * tg;
        float2 w00 = *(const float2*)ap;
        float2 w10 = *(const float2*)(ap + 8 * 256);
        float2 w01 = *(const float2*)(ap + 8);
        float2 w11 = *(const float2*)(ap + 8 * 256 + 8);
        uint4 u;
        u.x = pbf2(w00.x, w00.y);
        u.y = pbf2(w10.x, w10.y);
        u.z = pbf2(w01.x, w01.y);
        u.w = pbf2(w11.x, w11.y);
        dst[idx] = u;
    }
}

// ---------------- QKV GEMM: cp.async A-frags, GN-fused inline B ----------------
#define QKV_SMEM 35328

__global__ void __launch_bounds__(256) gemm_qkv(const float* __restrict__ x,
                                                const float* __restrict__ bias,
                                                const float* __restrict__ nw,
                                                const float* __restrict__ nbv) {
    extern __shared__ char sm[];
    uint32_t sb;
    asm("{ .reg .u64 t; cvta.to.shared.u64 t, %1; cvt.u32.u64 %0, t; }" : "=r"(sb) : "l"(sm));
    uint2* Bf = (uint2*)(sm + 8192);
    unsigned short* Ost = (unsigned short*)sm;
    float* sc = (float*)(sm + 33280);
    float* sh = (float*)(sm + 34304);

    const int tid = threadIdx.x, wid = tid >> 5, lane = tid & 31;
    const int gr = lane >> 2, tg = lane & 3;
    const int n0 = blockIdx.x * 128, mb = blockIdx.y, b = blockIdx.z;
    const int wm = wid & 3, wn = wid >> 2;

    {
        int c = tid;
        int bg = b * 8 + (c >> 5);
        float s_ = 0.f, q_ = 0.f;
#pragma unroll
        for (int i = 0; i < 16; i++) {
            s_ += g_part[(bg * 16 + i) * 2 + 0];
            q_ += g_part[(bg * 16 + i) * 2 + 1];
        }
        const float inv = 1.0f / 131072.0f;
        float mean = s_ * inv;
        float var = q_ * inv - mean * mean;
        float rstd = rsqrtf(var + EPSV);
        float s = rstd * nw[c];
        sc[c] = s;
        sh[c] = nbv[c] - mean * s;
    }

    float acc[2][8][4] = {};

    cp16(sb + tid * 16, g_wqf + (size_t)(mb * 16) * 256 + tid);
    CP_COMMIT();
    __syncthreads();

    for (int ks = 0; ks < 16; ks++) {
#pragma unroll
        for (int i = 0; i < 2; i++) {
            int u_ = wid * 2 + i;
            int n = n0 + u_ * 8 + gr;
            int c0 = ks * 16 + 2 * tg;
            const float* xp = x + ((size_t)(b * 256 + c0)) * 4096 + n;
            float h00 = xp[0] * sc[c0] + sh[c0];
            float h01 = xp[4096] * sc[c0 + 1] + sh[c0 + 1];
            float h10 = xp[8 * 4096] * sc[c0 + 8] + sh[c0 + 8];
            float h11 = xp[9 * 4096] * sc[c0 + 9] + sh[c0 + 9];
            uint2 v;
            v.x = pbf2(h00, h01);
            v.y = pbf2(h10, h11);
            Bf[u_ * 32 + lane] = v;
        }
        if (ks + 1 < 16)
            cp16(sb + ((ks + 1) & 1) * 4096 + tid * 16,
                 g_wqf + (size_t)(mb * 16 + ks + 1) * 256 + tid);
        CP_COMMIT();
        CP_WAIT1();
        __syncthreads();

        const uint4* AfS = (const uint4*)(sm + (ks & 1) * 4096);
        uint4 a0 = AfS[(wm * 2 + 0) * 32 + lane];
        uint4 a1 = AfS[(wm * 2 + 1) * 32 + lane];
#pragma unroll
        for (int u_ = 0; u_ < 8; u_++) {
            uint2 bb = Bf[(wn * 8 + u_) * 32 + lane];
            mma_bf16(acc[0][u_], a0.x, a0.y, a0.z, a0.w, bb.x, bb.y);
            mma_bf16(acc[1][u_], a1.x, a1.y, a1.z, a1.w, bb.x, bb.y);
        }
        __syncthreads();
    }

    const float scale = (mb < 2) ? 0.125f * 1.4426950408889634f : 1.0f;
    const bool v_half = (mb >= 4);
#pragma unroll
    for (int t = 0; t < 2; t++) {
        int o_l = wm * 32 + t * 16 + gr;
        float bi0 = bias[mb * 128 + o_l];
        float bi1 = bias[mb * 128 + o_l + 8];
#pragma unroll
        for (int u_ = 0; u_ < 8; u_++) {
            int n_l = wn * 64 + u_ * 8 + 2 * tg;
            float v00 = (acc[t][u_][0] + bi0) * scale, v01 = (acc[t][u_][1] + bi0) * scale;
            float v10 = (acc[t][u_][2] + bi1) * scale, v11 = (acc[t][u_][3] + bi1) * scale;
            uint32_t w0 = v_half ? ph2(v00, v01) : pbf2(v00, v01);
            uint32_t w1 = v_half ? ph2(v10, v11) : pbf2(v10, v11);
            *(uint32_t*)&Ost[o_l * 130 + n_l] = w0;
            *(uint32_t*)&Ost[(o_l + 8) * 130 + n_l] = w1;
        }
    }
    __syncthreads();

    if (mb < 2) {
#pragma unroll
        for (int p = 0; p < 32; p++) {
            int idx = tid + p * 256;
            int n = idx >> 6;
            int ho = (idx >> 5) & 1;
            int cw = idx & 31;
            unsigned short lo = Ost[(ho * 64 + 2 * cw) * 130 + n];
            unsigned short hi = Ost[(ho * 64 + 2 * cw + 1) * 130 + n];
            uint32_t val = (uint32_t)lo | ((uint32_t)hi << 16);
            int bh = b * 4 + mb * 2 + ho;
            ((uint32_t*)g_qb)[((size_t)bh * 4096 + n0 + n) * 32 + cw] = val;
        }
    } else if (mb < 4) {
#pragma unroll
        for (int p = 0; p < 8; p++) {
            int e = tid + p * 256;
            int ln = e & 31, sp = (e >> 5) & 1, kt = (e >> 6) & 15, ho = e >> 10;
            int egr = ln >> 2, etg = ln & 3;
            int n = kt * 8 + egr;
            uint4 r;
            {
                int c0 = ho * 64 + (2 * sp) * 16 + 2 * etg;
                r.x = (uint32_t)Ost[c0 * 130 + n] | ((uint32_t)Ost[(c0 + 1) * 130 + n] << 16);
                r.y = (uint32_t)Ost[(c0 + 8) * 130 + n] | ((uint32_t)Ost[(c0 + 9) * 130 + n] << 16);
            }
            {
                int c0 = ho * 64 + (2 * sp + 1) * 16 + 2 * etg;
                r.z = (uint32_t)Ost[c0 * 130 + n] | ((uint32_t)Ost[(c0 + 1) * 130 + n] << 16);
                r.w = (uint32_t)Ost[(c0 + 8) * 130 + n] | ((uint32_t)Ost[(c0 + 9) * 130 + n] << 16);
            }
            int bh = b * 4 + (mb & 1) * 2 + ho;
            g_kf4[(((size_t)bh * 512 + (n0 >> 3) + kt) * 2 + sp) * 32 + ln] = r;
        }
    } else {
        int chv = blockIdx.x;
#pragma unroll
        for (int p = 0; p < 8; p++) {
            int e = tid + p * 256;
            int ln = e & 31, sp = (e >> 5) & 3, ct = (e >> 7) & 7, ho = e >> 10;
            int egr = ln >> 2, etg = ln & 3;
            int c = ho * 64 + ct * 8 + egr;
            uint4 r;
            {
                int nn = (2 * sp) * 16 + 2 * etg;
                r.x = *(uint32_t*)&Ost[c * 130 + nn];
                r.y = *(uint32_t*)&Ost[c * 130 + nn + 8];
            }
            {
                int nn = (2 * sp + 1) * 16 + 2 * etg;
                r.z = *(uint32_t*)&Ost[c * 130 + nn];
                r.w = *(uint32_t*)&Ost[c * 130 + nn + 8];
            }
            int bh = b * 4 + (mb - 4) * 2 + ho;
            g_vf4[((((size_t)bh * 32 + chv) * 8 + ct) * 4 + sp) * 32 + ln] = r;
        }
    }
}

// ---------------- Proj GEMM: fully cp.async 3-stage ring ----------------
#define PROJ_SMEM 24576

__global__ void __launch_bounds__(256) gemm_proj(const float* __restrict__ bias,
                                                 const float* __restrict__ resid,
                                                 float* __restrict__ outp) {
    extern __shared__ char smp[];
    uint32_t sb;
    asm("{ .reg .u64 t; cvta.to.shared.u64 t, %1; cvt.u32.u64 %0, t; }" : "=r"(sb) : "l"(smp));
    const int tid = threadIdx.x, wid = tid >> 5, lane = tid & 31;
    const int gr = lane >> 2, tg = lane & 3;
    const int n0 = blockIdx.x * 128, mb = blockIdx.y, b = blockIdx.z;
    const int wm = wid & 3, wn = wid >> 2;

    float acc[2][8][4] = {};

#define PPREF(ks) do {                                                        \
        int _k = (ks);                                                       \
        if (_k < 16) {                                                       \
            uint32_t _st = sb + (uint32_t)(_k % 3) * 8192;                   \
            const uint4* _ga = g_wpf + (size_t)(mb * 16 + _k) * 256;         \
            const uint4* _gb = (const uint4*)(g_aof +                        \
                (((size_t)(b * 16 + _k) * 512 + (n0 >> 3)) * 32));           \
            cp16(_st + tid * 16, _ga + tid);                                 \
            cp16(_st + 4096 + tid * 16, _gb + tid);                          \
        }                                                                    \
        CP_COMMIT();                                                         \
    } while (0)

    PPREF(0);
    PPREF(1);

    for (int ks = 0; ks < 16; ks++) {
        CP_WAIT1();
        __syncthreads();
        PPREF(ks + 2);

        const uint4* AfS = (const uint4*)(smp + (ks % 3) * 8192);
        const uint2* BfS = (const uint2*)(smp + (ks % 3) * 8192 + 4096);
        uint4 a0 = AfS[(wm * 2 + 0) * 32 + lane];
        uint4 a1 = AfS[(wm * 2 + 1) * 32 + lane];
#pragma unroll
        for (int u_ = 0; u_ < 8; u_++) {
            uint2 bb = BfS[(wn * 8 + u_) * 32 + lane];
            mma_bf16(acc[0][u_], a0.x, a0.y, a0.z, a0.w, bb.x, bb.y);
            mma_bf16(acc[1][u_], a1.x, a1.y, a1.z, a1.w, bb.x, bb.y);
        }
    }
#undef PPREF

#pragma unroll
    for (int t = 0; t < 2; t++) {
        int o = mb * 128 + wm * 32 + t * 16 + gr;
        float bi0 = bias[o], bi1 = bias[o + 8];
#pragma unroll
        for (int u_ = 0; u_ < 8; u_++) {
            size_t off = ((size_t)(b * 256 + o)) * 4096 + n0 + wn * 64 + u_ * 8 + 2 * tg;
            float2 r0 = *(const float2*)(resid + off);
            float2 o0;
            o0.x = acc[t][u_][0] + bi0 + r0.x;
            o0.y = acc[t][u_][1] + bi0 + r0.y;
            *(float2*)(outp + off) = o0;
            size_t off8 = off + 8 * 4096;
            float2 r1 = *(const float2*)(resid + off8);
            float2 o1;
            o1.x = acc[t][u_][2] + bi1 + r1.x;
            o1.y = acc[t][u_][3] + bi1 + r1.y;
            *(float2*)(outp + off8) = o1;
        }
    }
}

// ---------------- flash attention: SPLIT-K halves (16 chunks/block) ----------------
// grid (64, 16): qt = bx & 31, half = bx >> 5. 128 thr, 2-stage ring, 3 CTAs/SM.
// Each block writes unnormalized partial O (fp16 pairs) + fp32 partial rowsums.
#define ATT_SMEM 65536
#define ONE2 0x3C003C00u

__global__ void __launch_bounds__(128, 3) attn_mma() {
    extern __shared__ char smc[];
    uint32_t sbase;
    asm("{ .reg .u64 t; cvta.to.shared.u64 t, %1; cvt.u32.u64 %0, t; }" : "=r"(sbase) : "l"(smc));

    const int tid = threadIdx.x, wid = tid >> 5, lane = tid & 31;
    const int gr = lane >> 2, tg = lane & 3;
    const int qt = blockIdx.x & 31, h = blockIdx.x >> 5, bh = blockIdx.y;
    const int w32 = wid * 32;
    const int ch0 = h << 4, chEnd = ch0 + 16;

    const __nv_bfloat16* qg = g_qb + ((size_t)bh * 4096 + qt * 128) * 64;
    const uint4* kfg = g_kf4 + (size_t)bh * 32768;
    const uint4* vfg = g_vf4 + (size_t)bh * 32768;

    uint32_t qa[2][4][4];
#pragma unroll
    for (int at = 0; at < 2; at++) {
#pragma unroll
        for (int s = 0; s < 4; s++) {
            const __nv_bfloat16* base = qg + (size_t)(w32 + at * 16 + gr) * 64 + s * 16 + 2 * tg;
            qa[at][s][0] = *(const uint32_t*)(base);
            qa[at][s][1] = *(const uint32_t*)(base + 8 * 64);
            qa[at][s][2] = *(const uint32_t*)(base + 8);
            qa[at][s][3] = *(const uint32_t*)(base + 8 * 64 + 8);
        }
    }

    float oacc[2][8][4] = {};
    float rsacc[2][4] = {};

#define PREFETCH(ch) do {                                                     \
        int _c = (ch);                                                       \
        if (_c < chEnd) {                                                    \
            uint32_t _sk = sbase + (uint32_t)(_c & 1) * 32768;               \
            const uint4* _gk = kfg + (size_t)_c * 1024;                      \
            const uint4* _gv = vfg + (size_t)_c * 1024;                      \
            _Pragma("unroll")                                                \
            for (int _i = 0; _i < 8; _i++)                                   \
                cp16(_sk + (tid + _i * 128) * 16, _gk + tid + _i * 128);     \
            _Pragma("unroll")                                                \
            for (int _i = 0; _i < 8; _i++)                                   \
                cp16(_sk + 16384 + (tid + _i * 128) * 16, _gv + tid + _i * 128); \
        }                                                                    \
        CP_COMMIT();                                                         \
    } while (0)

#define S_CALC(dst, g) do {                                                  \
        _Pragma("unroll")                                                    \
        for (int _u = 0; _u < 4; _u++) {                                     \
            uint4 _k0 = Kf4[(((g) * 4 + _u) * 2 + 0) * 32 + lane];           \
            uint4 _k1 = Kf4[(((g) * 4 + _u) * 2 + 1) * 32 + lane];           \
            _Pragma("unroll")                                                \
            for (int _at = 0; _at < 2; _at++) {                              \
                dst[_at][_u][0] = 0.f; dst[_at][_u][1] = 0.f;                \
                dst[_at][_u][2] = 0.f; dst[_at][_u][3] = 0.f;                \
                mma_bf16(dst[_at][_u], qa[_at][0][0], qa[_at][0][1], qa[_at][0][2], qa[_at][0][3], _k0.x, _k0.y); \
                mma_bf16(dst[_at][_u], qa[_at][1][0], qa[_at][1][1], qa[_at][1][2], qa[_at][1][3], _k0.z, _k0.w); \
                mma_bf16(dst[_at][_u], qa[_at][2][0], qa[_at][2][1], qa[_at][2][2], qa[_at][2][3], _k1.x, _k1.y); \
                mma_bf16(dst[_at][_u], qa[_at][3][0], qa[_at][3][1], qa[_at][3][2], qa[_at][3][3], _k1.z, _k1.w); \
            }                                                                \
        }                                                                    \
    } while (0)

#define E_CALC(pdst, src) do {                                               \
        _Pragma("unroll")                                                    \
        for (int _at = 0; _at < 2; _at++) {                                  \
            _Pragma("unroll")                                                \
            for (int _u = 0; _u < 4; _u++) {                                 \
                pdst[_at][_u][0] = ex2h2(ph2(src[_at][_u][0], src[_at][_u][1])); \
                pdst[_at][_u][1] = ex2h2(ph2(src[_at][_u][2], src[_at][_u][3])); \
            }                                                                \
        }                                                                    \
    } while (0)

#define V_CALC(g, psrc) do {                                                 \
        _Pragma("unroll")                                                    \
        for (int _ct = 0; _ct < 8; _ct++) {                                  \
            uint4 _v = Vf4[(_ct * 4 + (g)) * 32 + lane];                     \
            _Pragma("unroll")                                                \
            for (int _at = 0; _at < 2; _at++) {                              \
                mma_f16(oacc[_at][_ct], psrc[_at][0][0], psrc[_at][0][1],    \
                        psrc[_at][1][0], psrc[_at][1][1], _v.x, _v.y);       \
                mma_f16(oacc[_at][_ct], psrc[_at][2][0], psrc[_at][2][1],    \
                        psrc[_at][3][0], psrc[_at][3][1], _v.z, _v.w);       \
            }                                                                \
        }                                                                    \
        _Pragma("unroll")                                                    \
        for (int _at = 0; _at < 2; _at++) {                                  \
            mma_f16(rsacc[_at], psrc[_at][0][0], psrc[_at][0][1],            \
                    psrc[_at][1][0], psrc[_at][1][1], ONE2, ONE2);           \
            mma_f16(rsacc[_at], psrc[_at][2][0], psrc[_at][2][1],            \
                    psrc[_at][3][0], psrc[_at][3][1], ONE2, ONE2);           \
        }                                                                    \
    } while (0)

    PREFETCH(ch0);
    PREFETCH(ch0 + 1);

    for (int ch = ch0; ch < chEnd; ch++) {
        CP_WAIT1();
        __syncthreads();

        const uint4* Kf4 = (const uint4*)(smc + (ch & 1) * 32768);
        const uint4* Vf4 = (const uint4*)(smc + (ch & 1) * 32768 + 16384);

        float sA[2][4][4], sB[2][4][4];
        uint32_t pA[2][4][2], pB[2][4][2];

        S_CALC(sA, 0);
        E_CALC(pA, sA);
        S_CALC(sB, 1);
        V_CALC(0, pA);
        E_CALC(pB, sB);
        S_CALC(sA, 2);
        V_CALC(1, pB);
        E_CALC(pA, sA);
        S_CALC(sB, 3);
        V_CALC(2, pA);
        E_CALC(pB, sB);
        V_CALC(3, pB);

        __syncthreads();
        PREFETCH(ch + 2);
    }
#undef PREFETCH
#undef S_CALC
#undef E_CALC
#undef V_CALC

    // store partial O (fp16 pairs) + partial rowsums
    const int unit = ((bh * 32 + qt) << 1) + h;
    uint32_t* po = g_po + (size_t)unit * 4096;
#pragma unroll
    for (int at = 0; at < 2; at++) {
#pragma unroll
        for (int ct = 0; ct < 8; ct++) {
            po[(at * 16 + ct * 2 + 0) * 128 + tid] = ph2(oacc[at][ct][0], oacc[at][ct][1]);
            po[(at * 16 + ct * 2 + 1) * 128 + tid] = ph2(oacc[at][ct][2], oacc[at][ct][3]);
        }
    }
    float4 rsv;
    rsv.x = rsacc[0][0]; rsv.y = rsacc[0][2];
    rsv.z = rsacc[1][0]; rsv.w = rsacc[1][2];
    *(float4*)&g_prs[(size_t)unit * 512 + tid * 4] = rsv;
}

// ---------------- split-K combine: sum halves, normalize, write g_aof frags -------
__global__ void __launch_bounds__(128) attn_combine() {
    const int tid = threadIdx.x, wid = tid >> 5, lane = tid & 31;
    const int qt = blockIdx.x, bh = blockIdx.y;
    const int b = bh >> 2, hh = bh & 3;
    const size_t u0 = ((size_t)(bh * 32 + qt)) * 2;
    const uint32_t* p0 = g_po + u0 * 4096;
    const uint32_t* p1 = g_po + (u0 + 1) * 4096;

    float o[2][8][4];
#pragma unroll
    for (int at = 0; at < 2; at++) {
#pragma unroll
        for (int ct = 0; ct < 8; ct++) {
#pragma unroll
            for (int p = 0; p < 2; p++) {
                uint32_t a = p0[(at * 16 + ct * 2 + p) * 128 + tid];
                uint32_t c = p1[(at * 16 + ct * 2 + p) * 128 + tid];
                float2 fa = __half22float2(*(__half2*)&a);
                float2 fc = __half22float2(*(__half2*)&c);
                o[at][ct][2 * p] = fa.x + fc.x;
                o[at][ct][2 * p + 1] = fa.y + fc.y;
            }
        }
    }
    float4 r0 = *(const float4*)&g_prs[u0 * 512 + tid * 4];
    float4 r1 = *(const float4*)&g_prs[(u0 + 1) * 512 + tid * 4];
    float ri[2][2];
    ri[0][0] = 1.0f / (r0.x + r1.x);
    ri[0][1] = 1.0f / (r0.y + r1.y);
    ri[1][0] = 1.0f / (r0.z + r1.z);
    ri[1][1] = 1.0f / (r0.w + r1.w);

#pragma unroll
    for (int at = 0; at < 2; at++) {
        int nt0 = qt * 16 + wid * 4 + at * 2;
#pragma unroll
        for (int kgl = 0; kgl < 4; kgl++) {
            int kg = hh * 4 + kgl;
            uint2 f0, f1;
            f0.x = pbf2(o[at][2 * kgl][0] * ri[at][0], o[at][2 * kgl][1] * ri[at][0]);
            f0.y = pbf2(o[at][2 * kgl + 1][0] * ri[at][0], o[at][2 * kgl + 1][1] * ri[at][0]);
            f1.x = pbf2(o[at][2 * kgl][2] * ri[at][1], o[at][2 * kgl][3] * ri[at][1]);
            f1.y = pbf2(o[at][2 * kgl + 1][2] * ri[at][1], o[at][2 * kgl + 1][3] * ri[at][1]);
            size_t base = ((size_t)(b * 16 + kg) * 512 + nt0) * 32 + lane;
            g_aof[base] = f0;
            g_aof[base + 32] = f1;
        }
    }
}

// ---------------- launch ----------------
extern "C" void kernel_launch(void* const* d_in, const int* in_sizes, int n_in,
                              void* d_out, int out_size) {
    (void)in_sizes; (void)n_in; (void)out_size;
    const float* x      = (const float*)d_in[0];
    const float* norm_w = (const float*)d_in[1];
    const float* norm_b = (const float*)d_in[2];
    const float* qkv_w  = (const float*)d_in[3];
    const float* qkv_b  = (const float*)d_in[4];
    const float* proj_w = (const float*)d_in[5];
    const float* proj_b = (const float*)d_in[6];
    float* out = (float*)d_out;

    cudaFuncSetAttribute(attn_mma, cudaFuncAttributeMaxDynamicSharedMemorySize, ATT_SMEM);

    gn_wfrag<<<640, 256>>>(x, qkv_w, proj_w);

    gemm_qkv<<<dim3(32, 6, 4), 256, QKV_SMEM>>>(x, qkv_b, norm_w, norm_b);

    attn_mma<<<dim3(64, 16), 128, ATT_SMEM>>>();
    attn_combine<<<dim3(32, 16), 128>>>();

    gemm_proj<<<dim3(32, 2, 4), 256, PROJ_SMEM>>>(proj_b, x, out);
}